// round 5
// baseline (speedup 1.0000x reference)
#include <cuda_runtime.h>
#include <math.h>
#include <string.h>

// Problem constants
#define H_   16
#define D_   128
#define DM   2048   // H_*D_
#define NB   1024   // N_BASIS
#define MEM  512    // memory length (l)
#define QL   2048   // query length
#define NPOS 1024   // 2*l sample positions
#define BW   192    // half-bandwidth of F F^T + ridge (fp32 tails underflow beyond this)

// ----------------------------------------------------------------------------
// Device scratch (static globals -- no allocation anywhere)
// ----------------------------------------------------------------------------
__device__ float g_G[MEM * NB];      // G[l][n]
__device__ float g_B[NB * DM];       // B[n][e]
__device__ float g_keys[NB * DM];    // keysF[n][i] * (1/sqrt(D))
__device__ float g_vals[NB * DM];    // valsF[n][i]
__device__ float g_km[H_ * D_];      // sum_n keys[h][n][d]*w_mu[n]
__device__ float g_ks[H_ * D_];
__device__ float g_mu[H_ * QL];
__device__ float g_sg[H_ * QL];
__device__ float g_ctx[QL * DM];     // context[q][h*128+d]
__device__ float g_bmu[NB];
__device__ float g_bs2[NB];          // b_sigma^2

// ----------------------------------------------------------------------------
// Host-side constant computation: G = solve(F F^T + 0.5 I, F)^T [256:768]
// Pure function of compile-time constants; recomputed on every call
// (deterministic, no caching). Uploaded via captured memcpy nodes.
// ----------------------------------------------------------------------------
static double hF[NB][NPOS];
static double hA[NB][NB];            // holds banded Cholesky factor L in-place
static float  hostG[MEM * NB];
static float  hostbmu[NB], hostbs2[NB];

static void compute_G_host() {
    static double mu[NB], sgv[NB], pos[NPOS];
    static int plo[NB], phi[NB];
    const double SQ2PI = 2.506628274631000502;

    for (int i = 0; i < NB; i++) {
        mu[i]  = (double)(i >> 1) / 511.0;      // repeat(linspace(0,1,512), 2)
        sgv[i] = (i & 1) ? 0.01 : 0.005;        // tile([0.005, 0.01], 512)
        hostbmu[i] = (float)mu[i];
        hostbs2[i] = (float)(sgv[i] * sgv[i]);
    }
    double a = -0.5 + 1.0 / 1024.0;
    double b =  1.5 - 1.0 / 1024.0;
    double step = (b - a) / 1023.0;
    for (int p = 0; p < NPOS; p++) pos[p] = a + p * step;

    // F[i][p] = N(pos[p]; mu[i], sigma[i]); track nonzero window per row
    for (int i = 0; i < NB; i++) {
        int lo = NPOS, hi = -1;
        double inv = 1.0 / sgv[i];
        double amp = inv / SQ2PI;
        for (int p = 0; p < NPOS; p++) {
            double t = (pos[p] - mu[i]) * inv;
            if (t > -15.0 && t < 15.0) {
                hF[i][p] = exp(-0.5 * t * t) * amp;
                if (p < lo) lo = p;
                hi = p;
            } else hF[i][p] = 0.0;
        }
        plo[i] = lo; phi[i] = hi;
    }

    // A = F F^T + 0.5 I  (banded, symmetric)
    memset(hA, 0, sizeof(hA));
    for (int i = 0; i < NB; i++) {
        int jmax = (i + BW < NB) ? i + BW : NB - 1;
        for (int j = i; j <= jmax; j++) {
            int lo = plo[i] > plo[j] ? plo[i] : plo[j];
            int hi = phi[i] < phi[j] ? phi[i] : phi[j];
            double s = 0.0;
            for (int p = lo; p <= hi; p++) s += hF[i][p] * hF[j][p];
            hA[i][j] = s; hA[j][i] = s;
        }
        hA[i][i] += 0.5;
    }

    // banded Cholesky, lower, in place (bandwidth preserved; SPD since ridge>=0.5)
    for (int j = 0; j < NB; j++) {
        int kmin = (j - BW > 0) ? j - BW : 0;
        double s = hA[j][j];
        for (int k = kmin; k < j; k++) s -= hA[j][k] * hA[j][k];
        double Ljj = sqrt(s);
        hA[j][j] = Ljj;
        double invL = 1.0 / Ljj;
        int imax = (j + BW < NB) ? j + BW : NB - 1;
        for (int i = j + 1; i <= imax; i++) {
            int k0 = (i - BW > kmin) ? i - BW : kmin;
            double t = hA[i][j];
            for (int k = k0; k < j; k++) t -= hA[i][k] * hA[j][k];
            hA[i][j] = t * invL;
        }
    }

    // Solve A x = F[:,p] for p in [256,768) only (those are the kept rows of G^T)
    static double yv[NB], xv[NB];
    for (int p = 256; p < 768; p++) {
        for (int i = 0; i < NB; i++) {
            int k0 = (i - BW > 0) ? i - BW : 0;
            double s = hF[i][p];
            for (int k = k0; k < i; k++) s -= hA[i][k] * yv[k];
            yv[i] = s / hA[i][i];
        }
        for (int i = NB - 1; i >= 0; i--) {
            int k1 = (i + BW < NB) ? i + BW : NB - 1;
            double s = yv[i];
            for (int k = i + 1; k <= k1; k++) s -= hA[k][i] * xv[k];
            xv[i] = s / hA[i][i];
        }
        float* grow = &hostG[(p - 256) * NB];
        for (int n = 0; n < NB; n++) grow[n] = (float)xv[n];
    }
}

// ----------------------------------------------------------------------------
// Kernel 1: B[n][e] = sum_l G[l][n] * k[l][e]    (M=NB, N=DM, K=MEM)
// Both operands K-major-leading -> direct coalesced tile loads.
// ----------------------------------------------------------------------------
#define TBM 64
#define TBN 64
#define TBK 16

__global__ __launch_bounds__(256) void gemm_B_kernel(const float* __restrict__ kmat) {
    __shared__ float As[TBK][TBM];
    __shared__ float Bs[TBK][TBN];
    int m0 = blockIdx.x * TBM;   // n (basis)
    int n0 = blockIdx.y * TBN;   // e (model dim)
    int tx = threadIdx.x, ty = threadIdx.y;
    int tid = ty * 16 + tx;
    float acc[4][4] = {};

    for (int k0 = 0; k0 < MEM; k0 += TBK) {
        int row = tid >> 4;              // 0..15
        int col4 = (tid & 15) << 2;      // 0..60
        *reinterpret_cast<float4*>(&As[row][col4]) =
            *reinterpret_cast<const float4*>(&g_G[(k0 + row) * NB + m0 + col4]);
        *reinterpret_cast<float4*>(&Bs[row][col4]) =
            *reinterpret_cast<const float4*>(&kmat[(k0 + row) * DM + n0 + col4]);
        __syncthreads();
#pragma unroll
        for (int kk = 0; kk < TBK; kk++) {
            float4 a4 = *reinterpret_cast<float4*>(&As[kk][ty << 2]);
            float4 b4 = *reinterpret_cast<float4*>(&Bs[kk][tx << 2]);
            float av[4] = {a4.x, a4.y, a4.z, a4.w};
            float bv[4] = {b4.x, b4.y, b4.z, b4.w};
#pragma unroll
            for (int i = 0; i < 4; i++)
#pragma unroll
                for (int j = 0; j < 4; j++) acc[i][j] += av[i] * bv[j];
        }
        __syncthreads();
    }
    int mb = m0 + (ty << 2), nb = n0 + (tx << 2);
#pragma unroll
    for (int i = 0; i < 4; i++)
#pragma unroll
        for (int j = 0; j < 4; j++) g_B[(mb + i) * DM + nb + j] = acc[i][j];
}

// ----------------------------------------------------------------------------
// Kernel 2: generic NT GEMM: C[m][n] = scale * sum_k A[m][k]*Bm[n][k]
// A: M x K row-major (row stride K), Bm: N x K row-major, C row stride DM.
// ----------------------------------------------------------------------------
__global__ __launch_bounds__(256) void gemm_nt_kernel(
    const float* __restrict__ A, const float* __restrict__ Bm,
    float* __restrict__ C, int Kdim, float scale)
{
    __shared__ float As[TBK][TBM + 4];
    __shared__ float Bs[TBK][TBN + 4];
    int m0 = blockIdx.x * TBM;
    int n0 = blockIdx.y * TBN;
    int tx = threadIdx.x, ty = threadIdx.y;
    int tid = ty * 16 + tx;
    float acc[4][4] = {};

    int r  = tid >> 2;           // 0..63
    int c4 = (tid & 3) << 2;     // 0,4,8,12

    for (int k0 = 0; k0 < Kdim; k0 += TBK) {
        float4 va = *reinterpret_cast<const float4*>(&A[(m0 + r) * Kdim + k0 + c4]);
        As[c4 + 0][r] = va.x; As[c4 + 1][r] = va.y;
        As[c4 + 2][r] = va.z; As[c4 + 3][r] = va.w;
        float4 vb = *reinterpret_cast<const float4*>(&Bm[(n0 + r) * Kdim + k0 + c4]);
        Bs[c4 + 0][r] = vb.x; Bs[c4 + 1][r] = vb.y;
        Bs[c4 + 2][r] = vb.z; Bs[c4 + 3][r] = vb.w;
        __syncthreads();
#pragma unroll
        for (int kk = 0; kk < TBK; kk++) {
            float4 a4 = *reinterpret_cast<float4*>(&As[kk][ty << 2]);
            float4 b4 = *reinterpret_cast<float4*>(&Bs[kk][tx << 2]);
            float av[4] = {a4.x, a4.y, a4.z, a4.w};
            float bv[4] = {b4.x, b4.y, b4.z, b4.w};
#pragma unroll
            for (int i = 0; i < 4; i++)
#pragma unroll
                for (int j = 0; j < 4; j++) acc[i][j] += av[i] * bv[j];
        }
        __syncthreads();
    }
    int mb = m0 + (ty << 2), nb = n0 + (tx << 2);
#pragma unroll
    for (int i = 0; i < 4; i++)
#pragma unroll
        for (int j = 0; j < 4; j++) C[(mb + i) * DM + nb + j] = acc[i][j] * scale;
}

// ----------------------------------------------------------------------------
// Kernel 3: km[h][d] = sum_n keysS[h][n][d]*w_mu[n] ; same for ks with w_sigma
// ----------------------------------------------------------------------------
__global__ __launch_bounds__(1024) void kmks_kernel(
    const float* __restrict__ wmu, const float* __restrict__ wsig)
{
    __shared__ float red[2][8][128];
    int h = blockIdx.x;
    int dd = threadIdx.x;        // 0..127
    int t  = threadIdx.y;        // 0..7
    float sm = 0.f, ss = 0.f;
    for (int n = t; n < NB; n += 8) {
        float kv = g_keys[n * DM + h * D_ + dd];
        sm += kv * wmu[n];
        ss += kv * wsig[n];
    }
    red[0][t][dd] = sm; red[1][t][dd] = ss;
    __syncthreads();
    if (t == 0) {
        float a = 0.f, bsum = 0.f;
#pragma unroll
        for (int i = 0; i < 8; i++) { a += red[0][i][dd]; bsum += red[1][i][dd]; }
        g_km[h * D_ + dd] = a;
        g_ks[h * D_ + dd] = bsum;
    }
}

// ----------------------------------------------------------------------------
// Kernel 4: per (h,q): mu = sigmoid(q . km), sg = max(softplus(q . ks), 1e-4)
// one warp per row
// ----------------------------------------------------------------------------
__global__ __launch_bounds__(256) void musig_kernel(const float* __restrict__ q) {
    int warp = threadIdx.x >> 5, lane = threadIdx.x & 31;
    int row = blockIdx.x * 8 + warp;        // h*QL + q
    int h = row >> 11;                      // QL = 2048
    float4 qv = reinterpret_cast<const float4*>(q + (size_t)row * D_)[lane];
    float4 km = reinterpret_cast<const float4*>(g_km + h * D_)[lane];
    float4 ks = reinterpret_cast<const float4*>(g_ks + h * D_)[lane];
    float xm = qv.x * km.x + qv.y * km.y + qv.z * km.z + qv.w * km.w;
    float xs = qv.x * ks.x + qv.y * ks.y + qv.z * ks.z + qv.w * ks.w;
#pragma unroll
    for (int o = 16; o > 0; o >>= 1) {
        xm += __shfl_xor_sync(0xffffffffu, xm, o);
        xs += __shfl_xor_sync(0xffffffffu, xs, o);
    }
    if (lane == 0) {
        float m_ = 1.f / (1.f + expf(-xm));
        float sp = fmaxf(xs, 0.f) + log1pf(expf(-fabsf(xs)));   // stable softplus
        g_mu[row] = m_;
        g_sg[row] = fmaxf(sp, 1e-4f);
    }
}

// ----------------------------------------------------------------------------
// Kernel 5: fused r + context GEMM per head:
// ctx[q][h*128+d] = sum_n pdf(b_mu[n]; mu[h][q], sqrt(sg[h][q]+b_sig2[n])) * V[n][d]
// block: 64 q-rows x 128 d-cols; r tile computed on the fly in smem.
// ----------------------------------------------------------------------------
__global__ __launch_bounds__(256) void ctx_kernel() {
    __shared__ float Vs[TBK][D_];
    __shared__ float Rs[TBK][64 + 4];
    __shared__ float mus[64], sgs[64];
    __shared__ float bmu_s[TBK], bs2_s[TBK];

    int h = blockIdx.x;
    int q0 = blockIdx.y * 64;
    int tx = threadIdx.x;        // 0..31 -> d
    int ty = threadIdx.y;        // 0..7  -> q
    int tid = ty * 32 + tx;

    if (tid < 64) {
        mus[tid] = g_mu[h * QL + q0 + tid];
        sgs[tid] = g_sg[h * QL + q0 + tid];
    }

    float acc[8][4] = {};
    const float INV_SQRT_2PI = 0.3989422804014327f;

    for (int n0 = 0; n0 < NB; n0 += TBK) {
        {   // V tile: 16 x 128 floats = 512 float4, 2 per thread
            int e = tid;
            int rr = e >> 5, cc = (e & 31) << 2;
            *reinterpret_cast<float4*>(&Vs[rr][cc]) =
                *reinterpret_cast<const float4*>(&g_vals[(n0 + rr) * DM + h * D_ + cc]);
            e = tid + 256;
            rr = e >> 5; cc = (e & 31) << 2;
            *reinterpret_cast<float4*>(&Vs[rr][cc]) =
                *reinterpret_cast<const float4*>(&g_vals[(n0 + rr) * DM + h * D_ + cc]);
        }
        if (tid < TBK) { bmu_s[tid] = g_bmu[n0 + tid]; bs2_s[tid] = g_bs2[n0 + tid]; }
        __syncthreads();
        {   // r tile: 16 x 64, 4 per thread (same kk row, 4 consecutive q)
            int kk = tid >> 4;
            int qq = (tid & 15) << 2;
            float bm = bmu_s[kk], b2 = bs2_s[kk];
#pragma unroll
            for (int j = 0; j < 4; j++) {
                float s2 = sgs[qq + j] + b2;
                float inv = rsqrtf(s2);
                float t = (bm - mus[qq + j]) * inv;
                Rs[kk][qq + j] = expf(-0.5f * t * t) * inv * INV_SQRT_2PI;
            }
        }
        __syncthreads();
#pragma unroll
        for (int kk = 0; kk < TBK; kk++) {
            float4 v4 = *reinterpret_cast<float4*>(&Vs[kk][tx << 2]);
            float4 r0 = *reinterpret_cast<float4*>(&Rs[kk][ty << 3]);
            float4 r1 = *reinterpret_cast<float4*>(&Rs[kk][(ty << 3) + 4]);
            float rv[8] = {r0.x, r0.y, r0.z, r0.w, r1.x, r1.y, r1.z, r1.w};
            float vv[4] = {v4.x, v4.y, v4.z, v4.w};
#pragma unroll
            for (int i = 0; i < 8; i++)
#pragma unroll
                for (int j = 0; j < 4; j++) acc[i][j] += rv[i] * vv[j];
        }
        __syncthreads();
    }
    int qb = q0 + (ty << 3);
    int db = h * D_ + (tx << 2);
#pragma unroll
    for (int i = 0; i < 8; i++)
#pragma unroll
        for (int j = 0; j < 4; j++) g_ctx[(qb + i) * DM + db + j] = acc[i][j];
}

// ----------------------------------------------------------------------------
// launch
// ----------------------------------------------------------------------------
extern "C" void kernel_launch(void* const* d_in, const int* in_sizes, int n_in,
                              void* d_out, int out_size) {
    (void)in_sizes; (void)n_in; (void)out_size;
    const float* k_in = (const float*)d_in[0];   // [512, 2048]
    const float* q_in = (const float*)d_in[1];   // [16, 2048, 128]
    const float* Wk   = (const float*)d_in[2];   // [2048, 2048]
    const float* Wv   = (const float*)d_in[3];
    const float* Wo   = (const float*)d_in[4];
    const float* wmu  = (const float*)d_in[5];   // [1024]
    const float* wsig = (const float*)d_in[6];
    // d_in[7] = new_doc (unused by reference)

    // Input-independent constant; recomputed every call (no caching).
    compute_G_host();
    cudaMemcpyToSymbolAsync(g_G,   hostG,   sizeof(hostG),   0, cudaMemcpyHostToDevice, 0);
    cudaMemcpyToSymbolAsync(g_bmu, hostbmu, sizeof(hostbmu), 0, cudaMemcpyHostToDevice, 0);
    cudaMemcpyToSymbolAsync(g_bs2, hostbs2, sizeof(hostbs2), 0, cudaMemcpyHostToDevice, 0);

    float *pB, *pKeys, *pVals, *pCtx;
    cudaGetSymbolAddress((void**)&pB,    g_B);
    cudaGetSymbolAddress((void**)&pKeys, g_keys);
    cudaGetSymbolAddress((void**)&pVals, g_vals);
    cudaGetSymbolAddress((void**)&pCtx,  g_ctx);

    dim3 thr(16, 16);
    const float inv_sqrt_d = 0.08838834764831843f;   // 1/sqrt(128)

    gemm_B_kernel<<<dim3(NB / TBM, DM / TBN), thr>>>(k_in);
    gemm_nt_kernel<<<dim3(NB / TBM, DM / TBN), thr>>>(pB, Wk, pKeys, DM, inv_sqrt_d);
    gemm_nt_kernel<<<dim3(NB / TBM, DM / TBN), thr>>>(pB, Wv, pVals, DM, 1.0f);
    kmks_kernel<<<H_, dim3(128, 8)>>>(wmu, wsig);
    musig_kernel<<<(H_ * QL) / 8, 256>>>(q_in);
    ctx_kernel<<<dim3(H_, QL / 64), dim3(32, 8)>>>();
    gemm_nt_kernel<<<dim3(QL / TBM, DM / TBN), thr>>>(pCtx, Wo, (float*)d_out, DM, 1.0f);
}

// round 6
// speedup vs baseline: 1.2256x; 1.2256x over previous
#include <cuda_runtime.h>
#include <math.h>
#include <string.h>

// Problem constants
#define H_   16
#define D_   128
#define DM   2048   // H_*D_
#define NB   1024   // N_BASIS
#define MEM  512    // memory length (l)
#define QL   2048   // query length
#define NPOS 1024   // 2*l sample positions
#define BW   192    // half-bandwidth of F F^T + ridge

// GEMM tiling
#define BM 128
#define BN 128
#define BKK 16

// ----------------------------------------------------------------------------
// Device scratch (static globals -- no allocation anywhere)
// ----------------------------------------------------------------------------
__device__ float g_G[MEM * NB];      // G[l][n]
__device__ float g_B[NB * DM];       // B[n][e]
__device__ float g_keys[NB * DM];    // keys[n][i] * (1/sqrt(D))
__device__ float g_vals[NB * DM];
__device__ float g_km[H_ * D_];
__device__ float g_ks[H_ * D_];
__device__ float g_mu[H_ * QL];      // sigmoid mean
__device__ float g_amp[2][H_ * QL];  // invσ_p / sqrt(2π)
__device__ float g_c2[2][H_ * QL];   // -0.5 * invσ_p^2 * log2(e)
__device__ float g_ctx[QL * DM];
__device__ float g_bmu[NB];

// ----------------------------------------------------------------------------
// Host-side constant computation: G = solve(F F^T + 0.5 I, F)^T [256:768]
// Pure function of compile-time constants; recomputed on every call.
// ----------------------------------------------------------------------------
static double hF[NB][NPOS];
static double hA[NB][NB];
static float  hostG[MEM * NB];
static float  hostbmu[NB];

static void compute_G_host() {
    static double mu[NB], sgv[NB], pos[NPOS];
    static int plo[NB], phi[NB];
    const double SQ2PI = 2.506628274631000502;

    for (int i = 0; i < NB; i++) {
        mu[i]  = (double)(i >> 1) / 511.0;
        sgv[i] = (i & 1) ? 0.01 : 0.005;
        hostbmu[i] = (float)mu[i];
    }
    double a = -0.5 + 1.0 / 1024.0;
    double b =  1.5 - 1.0 / 1024.0;
    double step = (b - a) / 1023.0;
    for (int p = 0; p < NPOS; p++) pos[p] = a + p * step;

    for (int i = 0; i < NB; i++) {
        int lo = NPOS, hi = -1;
        double inv = 1.0 / sgv[i];
        double amp = inv / SQ2PI;
        for (int p = 0; p < NPOS; p++) {
            double t = (pos[p] - mu[i]) * inv;
            if (t > -15.0 && t < 15.0) {
                hF[i][p] = exp(-0.5 * t * t) * amp;
                if (p < lo) lo = p;
                hi = p;
            } else hF[i][p] = 0.0;
        }
        plo[i] = lo; phi[i] = hi;
    }

    memset(hA, 0, sizeof(hA));
    for (int i = 0; i < NB; i++) {
        int jmax = (i + BW < NB) ? i + BW : NB - 1;
        for (int j = i; j <= jmax; j++) {
            int lo = plo[i] > plo[j] ? plo[i] : plo[j];
            int hi = phi[i] < phi[j] ? phi[i] : phi[j];
            double s = 0.0;
            for (int p = lo; p <= hi; p++) s += hF[i][p] * hF[j][p];
            hA[i][j] = s; hA[j][i] = s;
        }
        hA[i][i] += 0.5;
    }

    for (int j = 0; j < NB; j++) {
        int kmin = (j - BW > 0) ? j - BW : 0;
        double s = hA[j][j];
        for (int k = kmin; k < j; k++) s -= hA[j][k] * hA[j][k];
        double Ljj = sqrt(s);
        hA[j][j] = Ljj;
        double invL = 1.0 / Ljj;
        int imax = (j + BW < NB) ? j + BW : NB - 1;
        for (int i = j + 1; i <= imax; i++) {
            int k0 = (i - BW > kmin) ? i - BW : kmin;
            double t = hA[i][j];
            for (int k = k0; k < j; k++) t -= hA[i][k] * hA[j][k];
            hA[i][j] = t * invL;
        }
    }

    static double yv[NB], xv[NB];
    for (int p = 256; p < 768; p++) {
        for (int i = 0; i < NB; i++) {
            int k0 = (i - BW > 0) ? i - BW : 0;
            double s = hF[i][p];
            for (int k = k0; k < i; k++) s -= hA[i][k] * yv[k];
            yv[i] = s / hA[i][i];
        }
        for (int i = NB - 1; i >= 0; i--) {
            int k1 = (i + BW < NB) ? i + BW : NB - 1;
            double s = yv[i];
            for (int k = i + 1; k <= k1; k++) s -= hA[k][i] * xv[k];
            xv[i] = s / hA[i][i];
        }
        float* grow = &hostG[(p - 256) * NB];
        for (int n = 0; n < NB; n++) grow[n] = (float)xv[n];
    }
}

// ----------------------------------------------------------------------------
// fast exp2 on the FMA pipe (x <= 0), no MUFU. ~2e-7 relative error.
// ----------------------------------------------------------------------------
__device__ __forceinline__ float fast_exp2(float x) {
    x = fmaxf(x, -126.0f);
    float fl = floorf(x);
    float f = x - fl;
    float p =        1.8775767e-3f;
    p = fmaf(p, f,   8.9893397e-3f);
    p = fmaf(p, f,   5.5826318e-2f);
    p = fmaf(p, f,   2.4015361e-1f);
    p = fmaf(p, f,   6.9315308e-1f);
    p = fmaf(p, f,   9.9999994e-1f);
    int e = __float2int_rn(fl);
    float s = __int_as_float((e + 127) << 23);
    return p * s;
}

// ----------------------------------------------------------------------------
// NT SGEMM: C[m][n] = scale * sum_k A[m][k] * Bm[n][k]
// A: MxK row-major, Bm: NxK row-major, C: row stride N.
// 128x128 block, 8x8 micro, BK=16, register-prefetch pipeline.
// ----------------------------------------------------------------------------
__global__ __launch_bounds__(256) void sgemm_nt(
    const float* __restrict__ A, const float* __restrict__ Bm,
    float* __restrict__ C, int N, int K, float scale)
{
    __shared__ float As[BKK][BM + 4];
    __shared__ float Bs[BKK][BN + 4];
    int m0 = blockIdx.x * BM, n0 = blockIdx.y * BN;
    int t = threadIdx.x;
    int ar = t >> 2;            // 0..63
    int kq = (t & 3) << 2;      // 0,4,8,12
    int tx = t & 15, ty = t >> 4;

    const float* pA0 = A + (size_t)(m0 + ar) * K + kq;
    const float* pA1 = A + (size_t)(m0 + ar + 64) * K + kq;
    const float* pB0 = Bm + (size_t)(n0 + ar) * K + kq;
    const float* pB1 = Bm + (size_t)(n0 + ar + 64) * K + kq;

    float4 fa0 = *(const float4*)pA0;
    float4 fa1 = *(const float4*)pA1;
    float4 fb0 = *(const float4*)pB0;
    float4 fb1 = *(const float4*)pB1;

    float acc[8][8] = {};

    for (int k0 = 0; k0 < K; k0 += BKK) {
        As[kq + 0][ar] = fa0.x; As[kq + 1][ar] = fa0.y;
        As[kq + 2][ar] = fa0.z; As[kq + 3][ar] = fa0.w;
        As[kq + 0][ar + 64] = fa1.x; As[kq + 1][ar + 64] = fa1.y;
        As[kq + 2][ar + 64] = fa1.z; As[kq + 3][ar + 64] = fa1.w;
        Bs[kq + 0][ar] = fb0.x; Bs[kq + 1][ar] = fb0.y;
        Bs[kq + 2][ar] = fb0.z; Bs[kq + 3][ar] = fb0.w;
        Bs[kq + 0][ar + 64] = fb1.x; Bs[kq + 1][ar + 64] = fb1.y;
        Bs[kq + 2][ar + 64] = fb1.z; Bs[kq + 3][ar + 64] = fb1.w;
        __syncthreads();
        if (k0 + BKK < K) {
            fa0 = *(const float4*)(pA0 + k0 + BKK);
            fa1 = *(const float4*)(pA1 + k0 + BKK);
            fb0 = *(const float4*)(pB0 + k0 + BKK);
            fb1 = *(const float4*)(pB1 + k0 + BKK);
        }
#pragma unroll
        for (int kk = 0; kk < BKK; kk++) {
            float4 a0 = *(float4*)&As[kk][ty << 3];
            float4 a1 = *(float4*)&As[kk][(ty << 3) + 4];
            float4 b0 = *(float4*)&Bs[kk][tx << 3];
            float4 b1 = *(float4*)&Bs[kk][(tx << 3) + 4];
            float av[8] = {a0.x, a0.y, a0.z, a0.w, a1.x, a1.y, a1.z, a1.w};
            float bv[8] = {b0.x, b0.y, b0.z, b0.w, b1.x, b1.y, b1.z, b1.w};
#pragma unroll
            for (int i = 0; i < 8; i++)
#pragma unroll
                for (int j = 0; j < 8; j++) acc[i][j] = fmaf(av[i], bv[j], acc[i][j]);
        }
        __syncthreads();
    }
    int mb = m0 + (ty << 3), nb = n0 + (tx << 3);
#pragma unroll
    for (int i = 0; i < 8; i++) {
        float4 o0 = make_float4(acc[i][0]*scale, acc[i][1]*scale, acc[i][2]*scale, acc[i][3]*scale);
        float4 o1 = make_float4(acc[i][4]*scale, acc[i][5]*scale, acc[i][6]*scale, acc[i][7]*scale);
        *(float4*)&C[(size_t)(mb + i) * N + nb]     = o0;
        *(float4*)&C[(size_t)(mb + i) * N + nb + 4] = o1;
    }
}

// ----------------------------------------------------------------------------
// TN SGEMM for B-projection: C[m][n] = sum_k A[k][m] * Bm[k][n]
// A: K x 1024 (G), Bm: K x 2048 (k), C: 1024 x 2048. Coalesced, no transpose.
// ----------------------------------------------------------------------------
__global__ __launch_bounds__(256) void sgemm_tn_B(
    const float* __restrict__ A, const float* __restrict__ Bm)
{
    __shared__ float As[BKK][BM + 4];
    __shared__ float Bs[BKK][BN + 4];
    int m0 = blockIdx.x * BM, n0 = blockIdx.y * BN;
    int t = threadIdx.x;
    int kr = t >> 4;            // 0..15
    int c4 = (t & 15) << 2;     // 0..60
    int tx = t & 15, ty = t >> 4;

    const float* pA = A + (size_t)kr * NB + m0 + c4;
    const float* pB = Bm + (size_t)kr * DM + n0 + c4;

    float4 fa0 = *(const float4*)pA;
    float4 fa1 = *(const float4*)(pA + 64);
    float4 fb0 = *(const float4*)pB;
    float4 fb1 = *(const float4*)(pB + 64);

    float acc[8][8] = {};

    for (int k0 = 0; k0 < MEM; k0 += BKK) {
        *(float4*)&As[kr][c4]      = fa0;
        *(float4*)&As[kr][c4 + 64] = fa1;
        *(float4*)&Bs[kr][c4]      = fb0;
        *(float4*)&Bs[kr][c4 + 64] = fb1;
        __syncthreads();
        if (k0 + BKK < MEM) {
            fa0 = *(const float4*)(pA + (size_t)(k0 + BKK) * NB);
            fa1 = *(const float4*)(pA + (size_t)(k0 + BKK) * NB + 64);
            fb0 = *(const float4*)(pB + (size_t)(k0 + BKK) * DM);
            fb1 = *(const float4*)(pB + (size_t)(k0 + BKK) * DM + 64);
        }
#pragma unroll
        for (int kk = 0; kk < BKK; kk++) {
            float4 a0 = *(float4*)&As[kk][ty << 3];
            float4 a1 = *(float4*)&As[kk][(ty << 3) + 4];
            float4 b0 = *(float4*)&Bs[kk][tx << 3];
            float4 b1 = *(float4*)&Bs[kk][(tx << 3) + 4];
            float av[8] = {a0.x, a0.y, a0.z, a0.w, a1.x, a1.y, a1.z, a1.w};
            float bv[8] = {b0.x, b0.y, b0.z, b0.w, b1.x, b1.y, b1.z, b1.w};
#pragma unroll
            for (int i = 0; i < 8; i++)
#pragma unroll
                for (int j = 0; j < 8; j++) acc[i][j] = fmaf(av[i], bv[j], acc[i][j]);
        }
        __syncthreads();
    }
    int mb = m0 + (ty << 3), nb = n0 + (tx << 3);
#pragma unroll
    for (int i = 0; i < 8; i++) {
        *(float4*)&g_B[(size_t)(mb + i) * DM + nb]     = *(float4*)&acc[i][0];
        *(float4*)&g_B[(size_t)(mb + i) * DM + nb + 4] = *(float4*)&acc[i][4];
    }
}

// ----------------------------------------------------------------------------
// km[h][d] = sum_n keys[h][n][d]*w_mu[n] ; ks likewise with w_sigma
// ----------------------------------------------------------------------------
__global__ __launch_bounds__(1024) void kmks_kernel(
    const float* __restrict__ wmu, const float* __restrict__ wsig)
{
    __shared__ float red[2][8][128];
    int h = blockIdx.x;
    int dd = threadIdx.x;
    int t  = threadIdx.y;
    float sm = 0.f, ss = 0.f;
    for (int n = t; n < NB; n += 8) {
        float kv = g_keys[n * DM + h * D_ + dd];
        sm += kv * wmu[n];
        ss += kv * wsig[n];
    }
    red[0][t][dd] = sm; red[1][t][dd] = ss;
    __syncthreads();
    if (t == 0) {
        float a = 0.f, bsum = 0.f;
#pragma unroll
        for (int i = 0; i < 8; i++) { a += red[0][i][dd]; bsum += red[1][i][dd]; }
        g_km[h * D_ + dd] = a;
        g_ks[h * D_ + dd] = bsum;
    }
}

// ----------------------------------------------------------------------------
// per (h,q): mu = sigmoid(q.km); sg = max(softplus(q.ks), 1e-4);
// then hoisted per-parity Gaussian params: amp_p, c_p.
// ----------------------------------------------------------------------------
__global__ __launch_bounds__(256) void musig_kernel(const float* __restrict__ q) {
    int warp = threadIdx.x >> 5, lane = threadIdx.x & 31;
    int row = blockIdx.x * 8 + warp;        // h*QL + q
    int h = row >> 11;
    float4 qv = reinterpret_cast<const float4*>(q + (size_t)row * D_)[lane];
    float4 km = reinterpret_cast<const float4*>(g_km + h * D_)[lane];
    float4 ks = reinterpret_cast<const float4*>(g_ks + h * D_)[lane];
    float xm = qv.x * km.x + qv.y * km.y + qv.z * km.z + qv.w * km.w;
    float xs = qv.x * ks.x + qv.y * ks.y + qv.z * ks.z + qv.w * ks.w;
#pragma unroll
    for (int o = 16; o > 0; o >>= 1) {
        xm += __shfl_xor_sync(0xffffffffu, xm, o);
        xs += __shfl_xor_sync(0xffffffffu, xs, o);
    }
    if (lane == 0) {
        const float INV_SQRT_2PI = 0.3989422804014327f;
        const float NHALF_LOG2E  = -0.7213475204444817f;   // -0.5*log2(e)
        float m_ = 1.f / (1.f + expf(-xm));
        float sp = fmaxf(xs, 0.f) + log1pf(expf(-fabsf(xs)));
        float sg = fmaxf(sp, 1e-4f);
        g_mu[row] = m_;
        float inv0 = rsqrtf(sg + 2.5e-5f);   // b_sigma=0.005 (even n)
        float inv1 = rsqrtf(sg + 1.0e-4f);   // b_sigma=0.01  (odd n)
        g_amp[0][row] = inv0 * INV_SQRT_2PI;
        g_amp[1][row] = inv1 * INV_SQRT_2PI;
        g_c2[0][row]  = NHALF_LOG2E * inv0 * inv0;
        g_c2[1][row]  = NHALF_LOG2E * inv1 * inv1;
    }
}

// ----------------------------------------------------------------------------
// Fused r + context GEMM per head (128 q x 128 d block, K=1024 over basis):
// ctx[q][h*128+d] = sum_n amp_p(q) * 2^(c_p(q)*(bmu[n]-mu[q])^2) * V[n][d]
// r tile computed on the FMA pipe (no MUFU).
// ----------------------------------------------------------------------------
__global__ __launch_bounds__(256) void ctx_kernel() {
    __shared__ float Rs[BKK][BM + 4];   // [n][q]
    __shared__ float Vs[BKK][BN + 4];   // [n][d]
    __shared__ float mus[128], amps[2][128], c2s[2][128];

    int qt = blockIdx.x;    // q tile
    int h  = blockIdx.y;
    int q0 = qt * 128;
    int t = threadIdx.x;
    int tx = t & 15, ty = t >> 4;

    if (t < 128) {
        int row = h * QL + q0 + t;
        mus[t]     = g_mu[row];
        amps[0][t] = g_amp[0][row];
        amps[1][t] = g_amp[1][row];
        c2s[0][t]  = g_c2[0][row];
        c2s[1][t]  = g_c2[1][row];
    }

    int vr = t >> 4;             // 0..15  (n within tile)
    int vc = (t & 15) << 2;      // 0..60
    int q8 = (t & 15) << 3;      // r-tile q offset for this thread
    const float* vbase = g_vals + h * D_;

    float acc[8][8] = {};
    __syncthreads();

    for (int n0 = 0; n0 < NB; n0 += BKK) {
        float4 v0 = *(const float4*)&vbase[(size_t)(n0 + vr) * DM + vc];
        float4 v1 = *(const float4*)&vbase[(size_t)(n0 + vr) * DM + vc + 64];
        // r tile: 8 consecutive q for basis index n0+vr
        int p = (n0 + vr) & 1;
        float bm = g_bmu[n0 + vr];
        float rloc[8];
#pragma unroll
        for (int j = 0; j < 8; j++) {
            float dx = bm - mus[q8 + j];
            float x = c2s[p][q8 + j] * dx * dx;
            rloc[j] = amps[p][q8 + j] * fast_exp2(x);
        }
        *(float4*)&Vs[vr][vc]      = v0;
        *(float4*)&Vs[vr][vc + 64] = v1;
#pragma unroll
        for (int j = 0; j < 8; j++) Rs[vr][q8 + j] = rloc[j];
        __syncthreads();
#pragma unroll
        for (int kk = 0; kk < BKK; kk++) {
            float4 a0 = *(float4*)&Rs[kk][ty << 3];
            float4 a1 = *(float4*)&Rs[kk][(ty << 3) + 4];
            float4 b0 = *(float4*)&Vs[kk][tx << 3];
            float4 b1 = *(float4*)&Vs[kk][(tx << 3) + 4];
            float av[8] = {a0.x, a0.y, a0.z, a0.w, a1.x, a1.y, a1.z, a1.w};
            float bv[8] = {b0.x, b0.y, b0.z, b0.w, b1.x, b1.y, b1.z, b1.w};
#pragma unroll
            for (int i = 0; i < 8; i++)
#pragma unroll
                for (int j = 0; j < 8; j++) acc[i][j] = fmaf(av[i], bv[j], acc[i][j]);
        }
        __syncthreads();
    }
    int qb = q0 + (ty << 3);
    int db = h * D_ + (tx << 3);
#pragma unroll
    for (int i = 0; i < 8; i++) {
        *(float4*)&g_ctx[(size_t)(qb + i) * DM + db]     = *(float4*)&acc[i][0];
        *(float4*)&g_ctx[(size_t)(qb + i) * DM + db + 4] = *(float4*)&acc[i][4];
    }
}

// ----------------------------------------------------------------------------
// launch
// ----------------------------------------------------------------------------
extern "C" void kernel_launch(void* const* d_in, const int* in_sizes, int n_in,
                              void* d_out, int out_size) {
    (void)in_sizes; (void)n_in; (void)out_size;
    const float* k_in = (const float*)d_in[0];   // [512, 2048]
    const float* q_in = (const float*)d_in[1];   // [16, 2048, 128]
    const float* Wk   = (const float*)d_in[2];   // [2048, 2048]
    const float* Wv   = (const float*)d_in[3];
    const float* Wo   = (const float*)d_in[4];
    const float* wmu  = (const float*)d_in[5];   // [1024]
    const float* wsig = (const float*)d_in[6];

    compute_G_host();
    cudaMemcpyToSymbolAsync(g_G,   hostG,   sizeof(hostG),   0, cudaMemcpyHostToDevice, 0);
    cudaMemcpyToSymbolAsync(g_bmu, hostbmu, sizeof(hostbmu), 0, cudaMemcpyHostToDevice, 0);

    float *pB, *pKeys, *pVals, *pCtx, *pG;
    cudaGetSymbolAddress((void**)&pB,    g_B);
    cudaGetSymbolAddress((void**)&pKeys, g_keys);
    cudaGetSymbolAddress((void**)&pVals, g_vals);
    cudaGetSymbolAddress((void**)&pCtx,  g_ctx);
    cudaGetSymbolAddress((void**)&pG,    g_G);

    const float inv_sqrt_d = 0.08838834764831843f;   // 1/sqrt(128)

    // B[n][e] = sum_l G[l][n] k[l][e]
    sgemm_tn_B<<<dim3(NB / BM, DM / BN), 256>>>(pG, k_in);
    // keys = (B Wk^T)/sqrt(D), vals = B Wv^T
    sgemm_nt<<<dim3(NB / BM, DM / BN), 256>>>(pB, Wk, pKeys, DM, DM, inv_sqrt_d);
    sgemm_nt<<<dim3(NB / BM, DM / BN), 256>>>(pB, Wv, pVals, DM, DM, 1.0f);
    kmks_kernel<<<H_, dim3(128, 8)>>>(wmu, wsig);
    musig_kernel<<<(H_ * QL) / 8, 256>>>(q_in);
    ctx_kernel<<<dim3(QL / BM, H_), 256>>>();
    // out = ctx Wo^T
    sgemm_nt<<<dim3(QL / BM, DM / BN), 256>>>(pCtx, Wo, (float*)d_out, DM, DM, 1.0f);
}

// round 8
// speedup vs baseline: 1.2286x; 1.0025x over previous
#include <cuda_runtime.h>
#include <cuda_bf16.h>
#include <math.h>
#include <string.h>
#include <stdint.h>

// Problem constants
#define H_   16
#define D_   128
#define DM   2048   // H_*D_
#define NB   1024   // N_BASIS
#define MEM  512    // memory length (l)
#define QL   2048   // query length
#define NPOS 1024   // 2*l sample positions
#define BW   192    // half-bandwidth of F F^T + ridge

// fp32 GEMM tiling (B-proj + ctx)
#define BM 128
#define BN 128
#define BKK 16

// mma GEMM tiling
#define GBK 16
#define GSTRIDE 24                       // smem row stride in bf16 (48B, conflict-free)
#define GTILE_E (128 * GSTRIDE)          // elems per tile
#define GTILE_B (GTILE_E * 2)            // bytes per tile
#define GSMEM_B (2 * 4 * GTILE_B)        // 2 stages x 4 tiles = 49152 B

// ----------------------------------------------------------------------------
// Device scratch (static globals -- no allocation anywhere)
// ----------------------------------------------------------------------------
__device__ float g_G[MEM * NB];
__device__ float g_B[NB * DM];
__device__ float g_keys[NB * DM];
__device__ float g_vals[NB * DM];
__device__ float g_km[H_ * D_];
__device__ float g_ks[H_ * D_];
__device__ float g_part[2][8][H_ * D_];
__device__ float g_mu[H_ * QL];
__device__ float g_amp[2][H_ * QL];
__device__ float g_c2[2][H_ * QL];
__device__ float g_ctx[QL * DM];
__device__ float g_bmu[NB];

// bf16 split operands
__device__ __nv_bfloat16 g_Bh[NB * DM],  g_Bl[NB * DM];
__device__ __nv_bfloat16 g_Wkh[DM * DM], g_Wkl[DM * DM];
__device__ __nv_bfloat16 g_Wvh[DM * DM], g_Wvl[DM * DM];
__device__ __nv_bfloat16 g_Woh[DM * DM], g_Wol[DM * DM];
__device__ __nv_bfloat16 g_Ch[QL * DM],  g_Cl[QL * DM];

// ----------------------------------------------------------------------------
// Host-side constant: G = solve(F F^T + 0.5 I, F)^T [256:768]
// ----------------------------------------------------------------------------
static double hF[NB][NPOS];
static double hA[NB][NB];
static float  hostG[MEM * NB];
static float  hostbmu[NB];

static void compute_G_host() {
    static double mu[NB], sgv[NB], pos[NPOS];
    static int plo[NB], phi[NB];
    const double SQ2PI = 2.506628274631000502;

    for (int i = 0; i < NB; i++) {
        mu[i]  = (double)(i >> 1) / 511.0;
        sgv[i] = (i & 1) ? 0.01 : 0.005;
        hostbmu[i] = (float)mu[i];
    }
    double a = -0.5 + 1.0 / 1024.0;
    double b =  1.5 - 1.0 / 1024.0;
    double step = (b - a) / 1023.0;
    for (int p = 0; p < NPOS; p++) pos[p] = a + p * step;

    for (int i = 0; i < NB; i++) {
        int lo = NPOS, hi = -1;
        double inv = 1.0 / sgv[i];
        double amp = inv / SQ2PI;
        for (int p = 0; p < NPOS; p++) {
            double t = (pos[p] - mu[i]) * inv;
            if (t > -15.0 && t < 15.0) {
                hF[i][p] = exp(-0.5 * t * t) * amp;
                if (p < lo) lo = p;
                hi = p;
            } else hF[i][p] = 0.0;
        }
        plo[i] = lo; phi[i] = hi;
    }

    memset(hA, 0, sizeof(hA));
    for (int i = 0; i < NB; i++) {
        int jmax = (i + BW < NB) ? i + BW : NB - 1;
        for (int j = i; j <= jmax; j++) {
            int lo = plo[i] > plo[j] ? plo[i] : plo[j];
            int hi = phi[i] < phi[j] ? phi[i] : phi[j];
            double s = 0.0;
            for (int p = lo; p <= hi; p++) s += hF[i][p] * hF[j][p];
            hA[i][j] = s; hA[j][i] = s;
        }
        hA[i][i] += 0.5;
    }

    for (int j = 0; j < NB; j++) {
        int kmin = (j - BW > 0) ? j - BW : 0;
        double s = hA[j][j];
        for (int k = kmin; k < j; k++) s -= hA[j][k] * hA[j][k];
        double Ljj = sqrt(s);
        hA[j][j] = Ljj;
        double invL = 1.0 / Ljj;
        int imax = (j + BW < NB) ? j + BW : NB - 1;
        for (int i = j + 1; i <= imax; i++) {
            int k0 = (i - BW > kmin) ? i - BW : kmin;
            double t = hA[i][j];
            for (int k = k0; k < j; k++) t -= hA[i][k] * hA[j][k];
            hA[i][j] = t * invL;
        }
    }

    static double yv[NB], xv[NB];
    for (int p = 256; p < 768; p++) {
        for (int i = 0; i < NB; i++) {
            int k0 = (i - BW > 0) ? i - BW : 0;
            double s = hF[i][p];
            for (int k = k0; k < i; k++) s -= hA[i][k] * yv[k];
            yv[i] = s / hA[i][i];
        }
        for (int i = NB - 1; i >= 0; i--) {
            int k1 = (i + BW < NB) ? i + BW : NB - 1;
            double s = yv[i];
            for (int k = i + 1; k <= k1; k++) s -= hA[k][i] * xv[k];
            xv[i] = s / hA[i][i];
        }
        float* grow = &hostG[(p - 256) * NB];
        for (int n = 0; n < NB; n++) grow[n] = (float)xv[n];
    }
}

// ----------------------------------------------------------------------------
// PTX helpers (all sm_80-portable: ldmatrix / mma.sync / cp.async)
// ----------------------------------------------------------------------------
__device__ __forceinline__ uint32_t smem_u32(const void* p) {
    uint32_t a;
    asm("{ .reg .u64 t; cvta.to.shared.u64 t, %1; cvt.u32.u64 %0, t; }" : "=r"(a) : "l"(p));
    return a;
}
__device__ __forceinline__ void cpa16(uint32_t s, const void* g) {
    asm volatile("cp.async.cg.shared.global [%0], [%1], 16;" :: "r"(s), "l"(g));
}
#define CP_COMMIT() asm volatile("cp.async.commit_group;" ::: "memory")
#define LDSM4(r0, r1, r2, r3, addr) \
    asm volatile("ldmatrix.sync.aligned.m8n8.x4.shared.b16 {%0,%1,%2,%3}, [%4];" \
                 : "=r"(r0), "=r"(r1), "=r"(r2), "=r"(r3) : "r"(addr))
#define MMA16816(c, a, b) \
    asm volatile("mma.sync.aligned.m16n8k16.row.col.f32.bf16.bf16.f32 " \
                 "{%0,%1,%2,%3}, {%4,%5,%6,%7}, {%8,%9}, {%0,%1,%2,%3};" \
                 : "+f"((c)[0]), "+f"((c)[1]), "+f"((c)[2]), "+f"((c)[3]) \
                 : "r"((a)[0]), "r"((a)[1]), "r"((a)[2]), "r"((a)[3]), \
                   "r"((b)[0]), "r"((b)[1]))

// ----------------------------------------------------------------------------
// Tensor-core NT GEMM with bf16 split operands:
// C[m][n] = scale * sum_k (Ahi+Alo)[m][k] * (Bhi+Blo)[n][k]  (lo*lo dropped)
// 128x128 CTA tile, 8 warps (4m x 2n), warp tile 32x64, BK=16,
// cp.async double buffer. Both operands K-contiguous -> no-trans ldmatrix.
// ----------------------------------------------------------------------------
__global__ __launch_bounds__(256) void gemm_mma_nt(
    const __nv_bfloat16* __restrict__ Ahi, const __nv_bfloat16* __restrict__ Alo,
    const __nv_bfloat16* __restrict__ Bhi, const __nv_bfloat16* __restrict__ Blo,
    float* __restrict__ C, int N, int K, float scale)
{
    extern __shared__ char smraw[];
    uint32_t base = smem_u32(smraw);

    int tid = threadIdx.x, lane = tid & 31, wid = tid >> 5;
    int m0 = blockIdx.x * 128, n0 = blockIdx.y * 128;
    int wm = (wid & 3) << 5;    // warp m offset (0..96)
    int wn = (wid >> 2) << 6;   // warp n offset (0 or 64)

    float acc[2][8][4];
#pragma unroll
    for (int i = 0; i < 2; i++)
#pragma unroll
        for (int j = 0; j < 8; j++)
#pragma unroll
            for (int l = 0; l < 4; l++) acc[i][j][l] = 0.f;

    // cp.async mapping: thread -> (row r, 16B half hf)
    int r = tid >> 1, hf = tid & 1;
    const __nv_bfloat16* gA0 = Ahi + (size_t)(m0 + r) * K + hf * 8;
    const __nv_bfloat16* gA1 = Alo + (size_t)(m0 + r) * K + hf * 8;
    const __nv_bfloat16* gB0 = Bhi + (size_t)(n0 + r) * K + hf * 8;
    const __nv_bfloat16* gB1 = Blo + (size_t)(n0 + r) * K + hf * 8;
    uint32_t soff = (uint32_t)(r * GSTRIDE + hf * 8) * 2;

    const int NT = K / GBK;

    // prefetch stage 0
    {
        uint32_t sb = base + soff;
        cpa16(sb,               gA0);
        cpa16(sb + GTILE_B,     gA1);
        cpa16(sb + 2 * GTILE_B, gB0);
        cpa16(sb + 3 * GTILE_B, gB1);
        CP_COMMIT();
    }

    // ldmatrix lane addressing (byte offsets within a tile)
    uint32_t a_off = ((uint32_t)((lane & 15)) * GSTRIDE + ((lane >> 4) << 3)) * 2;
    uint32_t b_off = ((uint32_t)((lane & 7) + ((lane & 16) ? 8 : 0)) * GSTRIDE +
                     ((lane & 8) ? 8 : 0)) * 2;

    for (int it = 0; it < NT; it++) {
        int s = it & 1;
        if (it + 1 < NT) {
            int k0 = (it + 1) * GBK;
            uint32_t sb = base + (s ^ 1) * (4 * GTILE_B) + soff;
            cpa16(sb,               gA0 + k0);
            cpa16(sb + GTILE_B,     gA1 + k0);
            cpa16(sb + 2 * GTILE_B, gB0 + k0);
            cpa16(sb + 3 * GTILE_B, gB1 + k0);
            CP_COMMIT();
            asm volatile("cp.async.wait_group 1;" ::: "memory");
        } else {
            asm volatile("cp.async.wait_group 0;" ::: "memory");
        }
        __syncthreads();

        uint32_t tb = base + s * (4 * GTILE_B);

        uint32_t ah[2][4], al[2][4];
        {
            uint32_t ad = tb + (uint32_t)wm * GSTRIDE * 2 + a_off;
            LDSM4(ah[0][0], ah[0][1], ah[0][2], ah[0][3], ad);
            LDSM4(ah[1][0], ah[1][1], ah[1][2], ah[1][3], ad + 16 * GSTRIDE * 2);
            uint32_t adl = ad + GTILE_B;
            LDSM4(al[0][0], al[0][1], al[0][2], al[0][3], adl);
            LDSM4(al[1][0], al[1][1], al[1][2], al[1][3], adl + 16 * GSTRIDE * 2);
        }
        uint32_t bh[8][2], bl[8][2];
        {
            uint32_t bd = tb + 2 * GTILE_B + (uint32_t)wn * GSTRIDE * 2 + b_off;
#pragma unroll
            for (int j = 0; j < 4; j++) {
                uint32_t ad = bd + (uint32_t)j * 16 * GSTRIDE * 2;
                LDSM4(bh[2 * j][0], bh[2 * j][1], bh[2 * j + 1][0], bh[2 * j + 1][1], ad);
                LDSM4(bl[2 * j][0], bl[2 * j][1], bl[2 * j + 1][0], bl[2 * j + 1][1],
                      ad + GTILE_B);
            }
        }

#pragma unroll
        for (int mt = 0; mt < 2; mt++)
#pragma unroll
            for (int nt = 0; nt < 8; nt++) {
                MMA16816(acc[mt][nt], ah[mt], bh[nt]);
                MMA16816(acc[mt][nt], ah[mt], bl[nt]);
                MMA16816(acc[mt][nt], al[mt], bh[nt]);
            }
        __syncthreads();   // protect stage s before it is refilled next iter
    }

    // epilogue
    float* Cp = C + (size_t)(m0 + wm) * N + n0 + wn;
    int erow = lane >> 2;
    int ecol = (lane & 3) << 1;
#pragma unroll
    for (int mt = 0; mt < 2; mt++)
#pragma unroll
        for (int nt = 0; nt < 8; nt++) {
            int row = mt * 16 + erow;
            int col = nt * 8 + ecol;
            float2 v0 = make_float2(acc[mt][nt][0] * scale, acc[mt][nt][1] * scale);
            float2 v1 = make_float2(acc[mt][nt][2] * scale, acc[mt][nt][3] * scale);
            *(float2*)&Cp[(size_t)row * N + col]       = v0;
            *(float2*)&Cp[(size_t)(row + 8) * N + col] = v1;
        }
}

// ----------------------------------------------------------------------------
// split fp32 -> bf16 hi/lo
// ----------------------------------------------------------------------------
__global__ __launch_bounds__(256) void split_kernel(
    const float4* __restrict__ src, __nv_bfloat162* __restrict__ hi,
    __nv_bfloat162* __restrict__ lo, int n4)
{
    int i = blockIdx.x * 256 + threadIdx.x;
    if (i >= n4) return;
    float4 v = src[i];
    __nv_bfloat16 h0 = __float2bfloat16(v.x);
    __nv_bfloat16 h1 = __float2bfloat16(v.y);
    __nv_bfloat16 h2 = __float2bfloat16(v.z);
    __nv_bfloat16 h3 = __float2bfloat16(v.w);
    __nv_bfloat16 l0 = __float2bfloat16(v.x - __bfloat162float(h0));
    __nv_bfloat16 l1 = __float2bfloat16(v.y - __bfloat162float(h1));
    __nv_bfloat16 l2 = __float2bfloat16(v.z - __bfloat162float(h2));
    __nv_bfloat16 l3 = __float2bfloat16(v.w - __bfloat162float(h3));
    hi[2 * i]     = __halves2bfloat162(h0, h1);
    hi[2 * i + 1] = __halves2bfloat162(h2, h3);
    lo[2 * i]     = __halves2bfloat162(l0, l1);
    lo[2 * i + 1] = __halves2bfloat162(l2, l3);
}

// ----------------------------------------------------------------------------
// fast exp2 on the FMA pipe (x <= 0), no MUFU.
// ----------------------------------------------------------------------------
__device__ __forceinline__ float fast_exp2(float x) {
    x = fmaxf(x, -126.0f);
    float fl = floorf(x);
    float f = x - fl;
    float p =        1.8775767e-3f;
    p = fmaf(p, f,   8.9893397e-3f);
    p = fmaf(p, f,   5.5826318e-2f);
    p = fmaf(p, f,   2.4015361e-1f);
    p = fmaf(p, f,   6.9315308e-1f);
    p = fmaf(p, f,   9.9999994e-1f);
    int e = __float2int_rn(fl);
    float s = __int_as_float((e + 127) << 23);
    return p * s;
}

// ----------------------------------------------------------------------------
// TN SGEMM for B-projection: g_B[m][n] = sum_k G[k][m] * kmat[k][n]
// ----------------------------------------------------------------------------
__global__ __launch_bounds__(256) void sgemm_tn_B(
    const float* __restrict__ A, const float* __restrict__ Bm)
{
    __shared__ float As[BKK][BM + 4];
    __shared__ float Bs[BKK][BN + 4];
    int m0 = blockIdx.x * BM, n0 = blockIdx.y * BN;
    int t = threadIdx.x;
    int kr = t >> 4;
    int c4 = (t & 15) << 2;
    int tx = t & 15, ty = t >> 4;

    const float* pA = A + (size_t)kr * NB + m0 + c4;
    const float* pB = Bm + (size_t)kr * DM + n0 + c4;

    float4 fa0 = *(const float4*)pA;
    float4 fa1 = *(const float4*)(pA + 64);
    float4 fb0 = *(const float4*)pB;
    float4 fb1 = *(const float4*)(pB + 64);

    float acc[8][8] = {};

    for (int k0 = 0; k0 < MEM; k0 += BKK) {
        *(float4*)&As[kr][c4]      = fa0;
        *(float4*)&As[kr][c4 + 64] = fa1;
        *(float4*)&Bs[kr][c4]      = fb0;
        *(float4*)&Bs[kr][c4 + 64] = fb1;
        __syncthreads();
        if (k0 + BKK < MEM) {
            fa0 = *(const float4*)(pA + (size_t)(k0 + BKK) * NB);
            fa1 = *(const float4*)(pA + (size_t)(k0 + BKK) * NB + 64);
            fb0 = *(const float4*)(pB + (size_t)(k0 + BKK) * DM);
            fb1 = *(const float4*)(pB + (size_t)(k0 + BKK) * DM + 64);
        }
#pragma unroll
        for (int kk = 0; kk < BKK; kk++) {
            float4 a0 = *(float4*)&As[kk][ty << 3];
            float4 a1 = *(float4*)&As[kk][(ty << 3) + 4];
            float4 b0 = *(float4*)&Bs[kk][tx << 3];
            float4 b1 = *(float4*)&Bs[kk][(tx << 3) + 4];
            float av[8] = {a0.x, a0.y, a0.z, a0.w, a1.x, a1.y, a1.z, a1.w};
            float bv[8] = {b0.x, b0.y, b0.z, b0.w, b1.x, b1.y, b1.z, b1.w};
#pragma unroll
            for (int i = 0; i < 8; i++)
#pragma unroll
                for (int j = 0; j < 8; j++) acc[i][j] = fmaf(av[i], bv[j], acc[i][j]);
        }
        __syncthreads();
    }
    int mb = m0 + (ty << 3), nb = n0 + (tx << 3);
#pragma unroll
    for (int i = 0; i < 8; i++) {
        *(float4*)&g_B[(size_t)(mb + i) * DM + nb]     = *(float4*)&acc[i][0];
        *(float4*)&g_B[(size_t)(mb + i) * DM + nb + 4] = *(float4*)&acc[i][4];
    }
}

// ----------------------------------------------------------------------------
// kmks two-stage: partials over 8 n-chunks, then reduce
// ----------------------------------------------------------------------------
__global__ __launch_bounds__(128) void kmks_part(
    const float* __restrict__ wmu, const float* __restrict__ wsig)
{
    int h = blockIdx.x, c = blockIdx.y, dd = threadIdx.x;
    float sm = 0.f, ss = 0.f;
    int nbeg = c * 128;
    for (int n = nbeg; n < nbeg + 128; n++) {
        float kv = g_keys[n * DM + h * D_ + dd];
        sm += kv * wmu[n];
        ss += kv * wsig[n];
    }
    g_part[0][c][h * D_ + dd] = sm;
    g_part[1][c][h * D_ + dd] = ss;
}

__global__ __launch_bounds__(128) void kmks_reduce() {
    int h = blockIdx.x, dd = threadIdx.x;
    float a = 0.f, b = 0.f;
#pragma unroll
    for (int c = 0; c < 8; c++) {
        a += g_part[0][c][h * D_ + dd];
        b += g_part[1][c][h * D_ + dd];
    }
    g_km[h * D_ + dd] = a;
    g_ks[h * D_ + dd] = b;
}

// ----------------------------------------------------------------------------
// per (h,q): mu = sigmoid(q.km); sg = max(softplus(q.ks), 1e-4);
// hoisted per-parity Gaussian params amp_p, c_p.
// ----------------------------------------------------------------------------
__global__ __launch_bounds__(256) void musig_kernel(const float* __restrict__ q) {
    int warp = threadIdx.x >> 5, lane = threadIdx.x & 31;
    int row = blockIdx.x * 8 + warp;
    int h = row >> 11;
    float4 qv = reinterpret_cast<const float4*>(q + (size_t)row * D_)[lane];
    float4 km = reinterpret_cast<const float4*>(g_km + h * D_)[lane];
    float4 ks = reinterpret_cast<const float4*>(g_ks + h * D_)[lane];
    float xm = qv.x * km.x + qv.y * km.y + qv.z * km.z + qv.w * km.w;
    float xs = qv.x * ks.x + qv.y * ks.y + qv.z * ks.z + qv.w * ks.w;
#pragma unroll
    for (int o = 16; o > 0; o >>= 1) {
        xm += __shfl_xor_sync(0xffffffffu, xm, o);
        xs += __shfl_xor_sync(0xffffffffu, xs, o);
    }
    if (lane == 0) {
        const float INV_SQRT_2PI = 0.3989422804014327f;
        const float NHALF_LOG2E  = -0.7213475204444817f;
        float m_ = 1.f / (1.f + expf(-xm));
        float sp = fmaxf(xs, 0.f) + log1pf(expf(-fabsf(xs)));
        float sg = fmaxf(sp, 1e-4f);
        g_mu[row] = m_;
        float inv0 = rsqrtf(sg + 2.5e-5f);
        float inv1 = rsqrtf(sg + 1.0e-4f);
        g_amp[0][row] = inv0 * INV_SQRT_2PI;
        g_amp[1][row] = inv1 * INV_SQRT_2PI;
        g_c2[0][row]  = NHALF_LOG2E * inv0 * inv0;
        g_c2[1][row]  = NHALF_LOG2E * inv1 * inv1;
    }
}

// ----------------------------------------------------------------------------
// Fused r + context GEMM per head (fp32 FFMA, fast_exp2 on FMA pipe)
// ----------------------------------------------------------------------------
__global__ __launch_bounds__(256) void ctx_kernel() {
    __shared__ float Rs[BKK][BM + 4];
    __shared__ float Vs[BKK][BN + 4];
    __shared__ float mus[128], amps[2][128], c2s[2][128];

    int qt = blockIdx.x;
    int h  = blockIdx.y;
    int q0 = qt * 128;
    int t = threadIdx.x;
    int tx = t & 15, ty = t >> 4;

    if (t < 128) {
        int row = h * QL + q0 + t;
        mus[t]     = g_mu[row];
        amps[0][t] = g_amp[0][row];
        amps[1][t] = g_amp[1][row];
        c2s[0][t]  = g_c2[0][row];
        c2s[1][t]  = g_c2[1][row];
    }

    int vr = t >> 4;
    int vc = (t & 15) << 2;
    int q8 = (t & 15) << 3;
    const float* vbase = g_vals + h * D_;

    float acc[8][8] = {};
    __syncthreads();

    for (int n0 = 0; n0 < NB; n0 += BKK) {
        float4 v0 = *(const float4*)&vbase[(size_t)(n0 + vr) * DM + vc];
        float4 v1 = *(const float4*)&vbase[(size_t)(n0 + vr) * DM + vc + 64];
        int p = (n0 + vr) & 1;
        float bm = g_bmu[n0 + vr];
        float rloc[8];
#pragma unroll
        for (int j = 0; j < 8; j++) {
            float dx = bm - mus[q8 + j];
            float x = c2s[p][q8 + j] * dx * dx;
            rloc[j] = amps[p][q8 + j] * fast_exp2(x);
        }
        *(float4*)&Vs[vr][vc]      = v0;
        *(float4*)&Vs[vr][vc + 64] = v1;
#pragma unroll
        for (int j = 0; j < 8; j++) Rs[vr][q8 + j] = rloc[j];
        __syncthreads();
#pragma unroll
        for (int kk = 0; kk < BKK; kk++) {
            float4 a0 = *(float4*)&Rs[kk][ty << 3];
            float4 a1 = *(float4*)&Rs[kk][(ty << 3) + 4];
            float4 b0 = *(float4*)&Vs[kk][tx << 3];
            float4 b1 = *(float4*)&Vs[kk][(tx << 3) + 4];
            float av[8] = {a0.x, a0.y, a0.z, a0.w, a1.x, a1.y, a1.z, a1.w};
            float bv[8] = {b0.x, b0.y, b0.z, b0.w, b1.x, b1.y, b1.z, b1.w};
#pragma unroll
            for (int i = 0; i < 8; i++)
#pragma unroll
                for (int j = 0; j < 8; j++) acc[i][j] = fmaf(av[i], bv[j], acc[i][j]);
        }
        __syncthreads();
    }
    int qb = q0 + (ty << 3);
    int db = h * D_ + (tx << 3);
#pragma unroll
    for (int i = 0; i < 8; i++) {
        *(float4*)&g_ctx[(size_t)(qb + i) * DM + db]     = *(float4*)&acc[i][0];
        *(float4*)&g_ctx[(size_t)(qb + i) * DM + db + 4] = *(float4*)&acc[i][4];
    }
}

// ----------------------------------------------------------------------------
// launch
// ----------------------------------------------------------------------------
extern "C" void kernel_launch(void* const* d_in, const int* in_sizes, int n_in,
                              void* d_out, int out_size) {
    (void)in_sizes; (void)n_in; (void)out_size;
    const float* k_in = (const float*)d_in[0];
    const float* q_in = (const float*)d_in[1];
    const float* Wk   = (const float*)d_in[2];
    const float* Wv   = (const float*)d_in[3];
    const float* Wo   = (const float*)d_in[4];
    const float* wmu  = (const float*)d_in[5];
    const float* wsig = (const float*)d_in[6];

    compute_G_host();
    cudaMemcpyToSymbolAsync(g_G,   hostG,   sizeof(hostG),   0, cudaMemcpyHostToDevice, 0);
    cudaMemcpyToSymbolAsync(g_bmu, hostbmu, sizeof(hostbmu), 0, cudaMemcpyHostToDevice, 0);

    float *pB, *pKeys, *pVals, *pCtx, *pG;
    cudaGetSymbolAddress((void**)&pB,    g_B);
    cudaGetSymbolAddress((void**)&pKeys, g_keys);
    cudaGetSymbolAddress((void**)&pVals, g_vals);
    cudaGetSymbolAddress((void**)&pCtx,  g_ctx);
    cudaGetSymbolAddress((void**)&pG,    g_G);
    __nv_bfloat16 *pBh, *pBl, *pWkh, *pWkl, *pWvh, *pWvl, *pWoh, *pWol, *pCh, *pCl;
    cudaGetSymbolAddress((void**)&pBh,  g_Bh);  cudaGetSymbolAddress((void**)&pBl,  g_Bl);
    cudaGetSymbolAddress((void**)&pWkh, g_Wkh); cudaGetSymbolAddress((void**)&pWkl, g_Wkl);
    cudaGetSymbolAddress((void**)&pWvh, g_Wvh); cudaGetSymbolAddress((void**)&pWvl, g_Wvl);
    cudaGetSymbolAddress((void**)&pWoh, g_Woh); cudaGetSymbolAddress((void**)&pWol, g_Wol);
    cudaGetSymbolAddress((void**)&pCh,  g_Ch);  cudaGetSymbolAddress((void**)&pCl,  g_Cl);

    cudaFuncSetAttribute(gemm_mma_nt,
                         cudaFuncAttributeMaxDynamicSharedMemorySize, GSMEM_B);

    const float inv_sqrt_d = 0.08838834764831843f;   // 1/sqrt(128)
    const int n4B = NB * DM / 4, n4W = DM * DM / 4, n4C = QL * DM / 4;

    // B[n][e] = sum_l G[l][n] k[l][e]   (fp32)
    sgemm_tn_B<<<dim3(NB / BM, DM / BN), 256>>>(pG, k_in);

    // splits
    split_kernel<<<(n4B + 255) / 256, 256>>>((const float4*)pB,
        (__nv_bfloat162*)pBh, (__nv_bfloat162*)pBl, n4B);
    split_kernel<<<(n4W + 255) / 256, 256>>>((const float4*)Wk,
        (__nv_bfloat162*)pWkh, (__nv_bfloat162*)pWkl, n4W);
    split_kernel<<<(n4W + 255) / 256, 256>>>((const float4*)Wv,
        (__nv_bfloat162*)pWvh, (__nv_bfloat162*)pWvl, n4W);
    split_kernel<<<(n4W + 255) / 256, 256>>>((const float4*)Wo,
        (__nv_bfloat162*)pWoh, (__nv_bfloat162*)pWol, n4W);

    // keys = (B Wk^T)/sqrt(D), vals = B Wv^T  -- tensor-core bf16-split
    gemm_mma_nt<<<dim3(NB / 128, DM / 128), 256, GSMEM_B>>>(
        pBh, pBl, pWkh, pWkl, pKeys, DM, DM, inv_sqrt_d);
    gemm_mma_nt<<<dim3(NB / 128, DM / 128), 256, GSMEM_B>>>(
        pBh, pBl, pWvh, pWvl, pVals, DM, DM, 1.0f);

    kmks_part<<<dim3(H_, 8), 128>>>(wmu, wsig);
    kmks_reduce<<<H_, 128>>>();
    musig_kernel<<<(H_ * QL) / 8, 256>>>(q_in);
    ctx_kernel<<<dim3(QL / BM, H_), 256>>>();

    // split ctx, then out = ctx Wo^T  -- tensor-core bf16-split
    split_kernel<<<(n4C + 255) / 256, 256>>>((const float4*)pCtx,
        (__nv_bfloat162*)pCh, (__nv_bfloat162*)pCl, n4C);
    gemm_mma_nt<<<dim3(QL / 128, DM / 128), 256, GSMEM_B>>>(
        pCh, pCl, pWoh, pWol, (float*)d_out, DM, DM, 1.0f);
}

// round 11
// speedup vs baseline: 2.2610x; 1.8403x over previous
#include <cuda_runtime.h>
#include <cuda_bf16.h>
#include <math.h>
#include <string.h>
#include <stdint.h>

// Problem constants
#define H_   16
#define D_   128
#define DM   2048   // H_*D_
#define NB   1024   // N_BASIS
#define MEM  512    // memory length (l)
#define QL   2048   // query length
#define NPOS 1024   // 2*l sample positions
#define BW   192    // half-bandwidth of F F^T + ridge

// fp32 GEMM tiling (B-proj + ctx)
#define BM 128
#define BN 128
#define BKK 16

// mma GEMM tiling
#define GBK 16
#define GSTRIDE 24                       // smem row stride in bf16 (48B, conflict-free)
#define GTILE_E (128 * GSTRIDE)          // elems per tile
#define GTILE_B (GTILE_E * 2)            // bytes per tile (6144)
#define STAGE_B (4 * GTILE_B)            // 4 tiles per stage (24576)
#define GSMEM_B (3 * STAGE_B)            // 3 stages = 73728 B

// ----------------------------------------------------------------------------
// Device scratch (static globals -- no allocation anywhere)
// ----------------------------------------------------------------------------
__device__ float g_G[MEM * NB];
__device__ float g_B[NB * DM];
__device__ float g_vals[NB * DM];
__device__ float g_km[DM];           // Wk . bv_mu / sqrt(D), row i = h*128+d
__device__ float g_ks[DM];
__device__ float g_pb[2][8][DM];     // bvec partials
__device__ float g_bvmu[DM];
__device__ float g_bvsg[DM];
__device__ float g_mu[H_ * QL];
__device__ float g_amp[2][H_ * QL];
__device__ float g_c2[2][H_ * QL];
__device__ float g_ctx[QL * DM];
__device__ float g_bmu[NB];

// bf16 split operands
__device__ __nv_bfloat16 g_Bh[NB * DM],  g_Bl[NB * DM];
__device__ __nv_bfloat16 g_Wvh[DM * DM], g_Wvl[DM * DM];
__device__ __nv_bfloat16 g_Woh[DM * DM], g_Wol[DM * DM];
__device__ __nv_bfloat16 g_Ch[QL * DM],  g_Cl[QL * DM];

// ----------------------------------------------------------------------------
// Host-side constant: G = solve(F F^T + 0.5 I, F)^T [256:768]
// ----------------------------------------------------------------------------
static double hF[NB][NPOS];
static double hA[NB][NB];
static float  hostG[MEM * NB];
static float  hostbmu[NB];

static void compute_G_host() {
    static double mu[NB], sgv[NB], pos[NPOS];
    static int plo[NB], phi[NB];
    const double SQ2PI = 2.506628274631000502;

    for (int i = 0; i < NB; i++) {
        mu[i]  = (double)(i >> 1) / 511.0;
        sgv[i] = (i & 1) ? 0.01 : 0.005;
        hostbmu[i] = (float)mu[i];
    }
    double a = -0.5 + 1.0 / 1024.0;
    double b =  1.5 - 1.0 / 1024.0;
    double step = (b - a) / 1023.0;
    for (int p = 0; p < NPOS; p++) pos[p] = a + p * step;

    for (int i = 0; i < NB; i++) {
        int lo = NPOS, hi = -1;
        double inv = 1.0 / sgv[i];
        double amp = inv / SQ2PI;
        for (int p = 0; p < NPOS; p++) {
            double t = (pos[p] - mu[i]) * inv;
            if (t > -15.0 && t < 15.0) {
                hF[i][p] = exp(-0.5 * t * t) * amp;
                if (p < lo) lo = p;
                hi = p;
            } else hF[i][p] = 0.0;
        }
        plo[i] = lo; phi[i] = hi;
    }

    memset(hA, 0, sizeof(hA));
    for (int i = 0; i < NB; i++) {
        int jmax = (i + BW < NB) ? i + BW : NB - 1;
        for (int j = i; j <= jmax; j++) {
            int lo = plo[i] > plo[j] ? plo[i] : plo[j];
            int hi = phi[i] < phi[j] ? phi[i] : phi[j];
            double s = 0.0;
            for (int p = lo; p <= hi; p++) s += hF[i][p] * hF[j][p];
            hA[i][j] = s; hA[j][i] = s;
        }
        hA[i][i] += 0.5;
    }

    for (int j = 0; j < NB; j++) {
        int kmin = (j - BW > 0) ? j - BW : 0;
        double s = hA[j][j];
        for (int k = kmin; k < j; k++) s -= hA[j][k] * hA[j][k];
        double Ljj = sqrt(s);
        hA[j][j] = Ljj;
        double invL = 1.0 / Ljj;
        int imax = (j + BW < NB) ? j + BW : NB - 1;
        for (int i = j + 1; i <= imax; i++) {
            int k0 = (i - BW > kmin) ? i - BW : kmin;
            double t = hA[i][j];
            for (int k = k0; k < j; k++) t -= hA[i][k] * hA[j][k];
            hA[i][j] = t * invL;
        }
    }

    static double yv[NB], xv[NB];
    for (int p = 256; p < 768; p++) {
        for (int i = 0; i < NB; i++) {
            int k0 = (i - BW > 0) ? i - BW : 0;
            double s = hF[i][p];
            for (int k = k0; k < i; k++) s -= hA[i][k] * yv[k];
            yv[i] = s / hA[i][i];
        }
        for (int i = NB - 1; i >= 0; i--) {
            int k1 = (i + BW < NB) ? i + BW : NB - 1;
            double s = yv[i];
            for (int k = i + 1; k <= k1; k++) s -= hA[k][i] * xv[k];
            xv[i] = s / hA[i][i];
        }
        float* grow = &hostG[(p - 256) * NB];
        for (int n = 0; n < NB; n++) grow[n] = (float)xv[n];
    }
}

// ----------------------------------------------------------------------------
// PTX helpers (sm_80-portable: ldmatrix / mma.sync / cp.async)
// ----------------------------------------------------------------------------
__device__ __forceinline__ uint32_t smem_u32(const void* p) {
    uint32_t a;
    asm("{ .reg .u64 t; cvta.to.shared.u64 t, %1; cvt.u32.u64 %0, t; }" : "=r"(a) : "l"(p));
    return a;
}
__device__ __forceinline__ void cpa16(uint32_t s, const void* g) {
    asm volatile("cp.async.cg.shared.global [%0], [%1], 16;" :: "r"(s), "l"(g));
}
#define CP_COMMIT() asm volatile("cp.async.commit_group;" ::: "memory")
#define LDSM4(r0, r1, r2, r3, addr) \
    asm volatile("ldmatrix.sync.aligned.m8n8.x4.shared.b16 {%0,%1,%2,%3}, [%4];" \
                 : "=r"(r0), "=r"(r1), "=r"(r2), "=r"(r3) : "r"(addr))
#define MMA16816(c, a, b) \
    asm volatile("mma.sync.aligned.m16n8k16.row.col.f32.bf16.bf16.f32 " \
                 "{%0,%1,%2,%3}, {%4,%5,%6,%7}, {%8,%9}, {%0,%1,%2,%3};" \
                 : "+f"((c)[0]), "+f"((c)[1]), "+f"((c)[2]), "+f"((c)[3]) \
                 : "r"((a)[0]), "r"((a)[1]), "r"((a)[2]), "r"((a)[3]), \
                   "r"((b)[0]), "r"((b)[1]))

// ----------------------------------------------------------------------------
// Tensor-core NT GEMM with bf16 split operands (3-stage cp.async pipeline):
// C[m][n] = scale * sum_k (Ahi+Alo)[m][k] * (Bhi+Blo)[n][k]  (lo*lo dropped)
// 128x128 CTA tile, 8 warps (4m x 2n), warp tile 32x64, BK=16.
// One __syncthreads per iteration; 2-iteration prefetch depth.
// ----------------------------------------------------------------------------
__global__ __launch_bounds__(256) void gemm_mma_nt(
    const __nv_bfloat16* __restrict__ Ahi, const __nv_bfloat16* __restrict__ Alo,
    const __nv_bfloat16* __restrict__ Bhi, const __nv_bfloat16* __restrict__ Blo,
    float* __restrict__ C, int N, int K, float scale)
{
    extern __shared__ char smraw[];
    uint32_t base = smem_u32(smraw);

    int tid = threadIdx.x, lane = tid & 31, wid = tid >> 5;
    int m0 = blockIdx.x * 128, n0 = blockIdx.y * 128;
    int wm = (wid & 3) << 5;    // warp m offset
    int wn = (wid >> 2) << 6;   // warp n offset

    float acc[2][8][4];
#pragma unroll
    for (int i = 0; i < 2; i++)
#pragma unroll
        for (int j = 0; j < 8; j++)
#pragma unroll
            for (int l = 0; l < 4; l++) acc[i][j][l] = 0.f;

    // cp.async mapping: thread -> (row r, 16B half hf)
    int r = tid >> 1, hf = tid & 1;
    const __nv_bfloat16* gA0 = Ahi + (size_t)(m0 + r) * K + hf * 8;
    const __nv_bfloat16* gA1 = Alo + (size_t)(m0 + r) * K + hf * 8;
    const __nv_bfloat16* gB0 = Bhi + (size_t)(n0 + r) * K + hf * 8;
    const __nv_bfloat16* gB1 = Blo + (size_t)(n0 + r) * K + hf * 8;
    uint32_t soff = (uint32_t)(r * GSTRIDE + hf * 8) * 2;

    const int NT = K / GBK;

    // prologue: stages 0,1
#pragma unroll
    for (int p = 0; p < 2; p++) {
        uint32_t sb = base + p * STAGE_B + soff;
        int k0 = p * GBK;
        cpa16(sb,               gA0 + k0);
        cpa16(sb + GTILE_B,     gA1 + k0);
        cpa16(sb + 2 * GTILE_B, gB0 + k0);
        cpa16(sb + 3 * GTILE_B, gB1 + k0);
        CP_COMMIT();
    }

    // ldmatrix lane addressing (byte offsets within a tile)
    uint32_t a_off = ((uint32_t)((lane & 15)) * GSTRIDE + ((lane >> 4) << 3)) * 2;
    uint32_t b_off = ((uint32_t)((lane & 7) + ((lane & 16) ? 8 : 0)) * GSTRIDE +
                     ((lane & 8) ? 8 : 0)) * 2;

    int s = 0;
    for (int it = 0; it < NT; it++) {
        asm volatile("cp.async.wait_group 1;" ::: "memory");
        __syncthreads();

        // prefetch stage it+2 (the stage consumed at it-1; all warps are past it)
        if (it + 2 < NT) {
            int s2 = s + 2; if (s2 >= 3) s2 -= 3;
            uint32_t sb = base + s2 * STAGE_B + soff;
            int k0 = (it + 2) * GBK;
            cpa16(sb,               gA0 + k0);
            cpa16(sb + GTILE_B,     gA1 + k0);
            cpa16(sb + 2 * GTILE_B, gB0 + k0);
            cpa16(sb + 3 * GTILE_B, gB1 + k0);
        }
        CP_COMMIT();   // empty group in the tail keeps wait_group(1) aligned

        uint32_t tb = base + s * STAGE_B;

        uint32_t ah[2][4], al[2][4];
        {
            uint32_t ad = tb + (uint32_t)wm * GSTRIDE * 2 + a_off;
            LDSM4(ah[0][0], ah[0][1], ah[0][2], ah[0][3], ad);
            LDSM4(ah[1][0], ah[1][1], ah[1][2], ah[1][3], ad + 16 * GSTRIDE * 2);
            uint32_t adl = ad + GTILE_B;
            LDSM4(al[0][0], al[0][1], al[0][2], al[0][3], adl);
            LDSM4(al[1][0], al[1][1], al[1][2], al[1][3], adl + 16 * GSTRIDE * 2);
        }
        uint32_t bh[8][2], bl[8][2];
        {
            uint32_t bd = tb + 2 * GTILE_B + (uint32_t)wn * GSTRIDE * 2 + b_off;
#pragma unroll
            for (int j = 0; j < 4; j++) {
                uint32_t ad = bd + (uint32_t)j * 16 * GSTRIDE * 2;
                LDSM4(bh[2 * j][0], bh[2 * j][1], bh[2 * j + 1][0], bh[2 * j + 1][1], ad);
                LDSM4(bl[2 * j][0], bl[2 * j][1], bl[2 * j + 1][0], bl[2 * j + 1][1],
                      ad + GTILE_B);
            }
        }

#pragma unroll
        for (int mt = 0; mt < 2; mt++)
#pragma unroll
            for (int nt = 0; nt < 8; nt++) {
                MMA16816(acc[mt][nt], ah[mt], bh[nt]);
                MMA16816(acc[mt][nt], ah[mt], bl[nt]);
                MMA16816(acc[mt][nt], al[mt], bh[nt]);
            }
        s++; if (s >= 3) s -= 3;
    }

    // epilogue
    float* Cp = C + (size_t)(m0 + wm) * N + n0 + wn;
    int erow = lane >> 2;
    int ecol = (lane & 3) << 1;
#pragma unroll
    for (int mt = 0; mt < 2; mt++)
#pragma unroll
        for (int nt = 0; nt < 8; nt++) {
            int row = mt * 16 + erow;
            int col = nt * 8 + ecol;
            float2 v0 = make_float2(acc[mt][nt][0] * scale, acc[mt][nt][1] * scale);
            float2 v1 = make_float2(acc[mt][nt][2] * scale, acc[mt][nt][3] * scale);
            *(float2*)&Cp[(size_t)row * N + col]       = v0;
            *(float2*)&Cp[(size_t)(row + 8) * N + col] = v1;
        }
}

// ----------------------------------------------------------------------------
// split fp32 -> bf16 hi/lo
// ----------------------------------------------------------------------------
__global__ __launch_bounds__(256) void split_kernel(
    const float4* __restrict__ src, __nv_bfloat162* __restrict__ hi,
    __nv_bfloat162* __restrict__ lo, int n4)
{
    int i = blockIdx.x * 256 + threadIdx.x;
    if (i >= n4) return;
    float4 v = src[i];
    __nv_bfloat16 h0 = __float2bfloat16(v.x);
    __nv_bfloat16 h1 = __float2bfloat16(v.y);
    __nv_bfloat16 h2 = __float2bfloat16(v.z);
    __nv_bfloat16 h3 = __float2bfloat16(v.w);
    __nv_bfloat16 l0 = __float2bfloat16(v.x - __bfloat162float(h0));
    __nv_bfloat16 l1 = __float2bfloat16(v.y - __bfloat162float(h1));
    __nv_bfloat16 l2 = __float2bfloat16(v.z - __bfloat162float(h2));
    __nv_bfloat16 l3 = __float2bfloat16(v.w - __bfloat162float(h3));
    hi[2 * i]     = __halves2bfloat162(h0, h1);
    hi[2 * i + 1] = __halves2bfloat162(h2, h3);
    lo[2 * i]     = __halves2bfloat162(l0, l1);
    lo[2 * i + 1] = __halves2bfloat162(l2, l3);
}

// ----------------------------------------------------------------------------
// fast exp2 on the FMA pipe (x <= 0), no MUFU.
// ----------------------------------------------------------------------------
__device__ __forceinline__ float fast_exp2(float x) {
    x = fmaxf(x, -126.0f);
    float fl = floorf(x);
    float f = x - fl;
    float p =        1.8775767e-3f;
    p = fmaf(p, f,   8.9893397e-3f);
    p = fmaf(p, f,   5.5826318e-2f);
    p = fmaf(p, f,   2.4015361e-1f);
    p = fmaf(p, f,   6.9315308e-1f);
    p = fmaf(p, f,   9.9999994e-1f);
    int e = __float2int_rn(fl);
    float s = __int_as_float((e + 127) << 23);
    return p * s;
}

// ----------------------------------------------------------------------------
// TN SGEMM for B-projection: g_B[m][n] = sum_k G[k][m] * kmat[k][n]
// ----------------------------------------------------------------------------
__global__ __launch_bounds__(256) void sgemm_tn_B(
    const float* __restrict__ A, const float* __restrict__ Bm)
{
    __shared__ float As[BKK][BM + 4];
    __shared__ float Bs[BKK][BN + 4];
    int m0 = blockIdx.x * BM, n0 = blockIdx.y * BN;
    int t = threadIdx.x;
    int kr = t >> 4;
    int c4 = (t & 15) << 2;
    int tx = t & 15, ty = t >> 4;

    const float* pA = A + (size_t)kr * NB + m0 + c4;
    const float* pB = Bm + (size_t)kr * DM + n0 + c4;

    float4 fa0 = *(const float4*)pA;
    float4 fa1 = *(const float4*)(pA + 64);
    float4 fb0 = *(const float4*)pB;
    float4 fb1 = *(const float4*)(pB + 64);

    float acc[8][8] = {};

    for (int k0 = 0; k0 < MEM; k0 += BKK) {
        *(float4*)&As[kr][c4]      = fa0;
        *(float4*)&As[kr][c4 + 64] = fa1;
        *(float4*)&Bs[kr][c4]      = fb0;
        *(float4*)&Bs[kr][c4 + 64] = fb1;
        __syncthreads();
        if (k0 + BKK < MEM) {
            fa0 = *(const float4*)(pA + (size_t)(k0 + BKK) * NB);
            fa1 = *(const float4*)(pA + (size_t)(k0 + BKK) * NB + 64);
            fb0 = *(const float4*)(pB + (size_t)(k0 + BKK) * DM);
            fb1 = *(const float4*)(pB + (size_t)(k0 + BKK) * DM + 64);
        }
#pragma unroll
        for (int kk = 0; kk < BKK; kk++) {
            float4 a0 = *(float4*)&As[kk][ty << 3];
            float4 a1 = *(float4*)&As[kk][(ty << 3) + 4];
            float4 b0 = *(float4*)&Bs[kk][tx << 3];
            float4 b1 = *(float4*)&Bs[kk][(tx << 3) + 4];
            float av[8] = {a0.x, a0.y, a0.z, a0.w, a1.x, a1.y, a1.z, a1.w};
            float bv[8] = {b0.x, b0.y, b0.z, b0.w, b1.x, b1.y, b1.z, b1.w};
#pragma unroll
            for (int i = 0; i < 8; i++)
#pragma unroll
                for (int j = 0; j < 8; j++) acc[i][j] = fmaf(av[i], bv[j], acc[i][j]);
        }
        __syncthreads();
    }
    int mb = m0 + (ty << 3), nb = n0 + (tx << 3);
#pragma unroll
    for (int i = 0; i < 8; i++) {
        *(float4*)&g_B[(size_t)(mb + i) * DM + nb]     = *(float4*)&acc[i][0];
        *(float4*)&g_B[(size_t)(mb + i) * DM + nb + 4] = *(float4*)&acc[i][4];
    }
}

// ----------------------------------------------------------------------------
// bvec: bv_mu[e] = sum_n B[n][e]*wmu[n], bv_sg likewise. Two-stage partials.
// ----------------------------------------------------------------------------
__global__ __launch_bounds__(128) void bvec_part(
    const float* __restrict__ wmu, const float* __restrict__ wsig)
{
    int e = blockIdx.x * 128 + threadIdx.x;
    int c = blockIdx.y;
    float sm = 0.f, ss = 0.f;
    int nbeg = c * 128;
    for (int n = nbeg; n < nbeg + 128; n++) {
        float b = g_B[(size_t)n * DM + e];
        sm += b * wmu[n];
        ss += b * wsig[n];
    }
    g_pb[0][c][e] = sm;
    g_pb[1][c][e] = ss;
}

__global__ __launch_bounds__(128) void bvec_reduce() {
    int e = blockIdx.x * 128 + threadIdx.x;
    float a = 0.f, b = 0.f;
#pragma unroll
    for (int c = 0; c < 8; c++) { a += g_pb[0][c][e]; b += g_pb[1][c][e]; }
    g_bvmu[e] = a;
    g_bvsg[e] = b;
}

// ----------------------------------------------------------------------------
// km[i] = (Wk[i,:] . bv_mu)/sqrt(D), ks[i] = (Wk[i,:] . bv_sg)/sqrt(D)
// one warp per row; single pass over Wk.
// ----------------------------------------------------------------------------
__global__ __launch_bounds__(256) void kmdot_kernel(const float* __restrict__ Wk) {
    int warp = threadIdx.x >> 5, lane = threadIdx.x & 31;
    int row = blockIdx.x * 8 + warp;
    const float4* w4 = (const float4*)(Wk + (size_t)row * DM);
    const float4* m4 = (const float4*)g_bvmu;
    const float4* s4 = (const float4*)g_bvsg;
    float xm = 0.f, xs = 0.f;
#pragma unroll
    for (int it = 0; it < 16; it++) {
        int idx = it * 32 + lane;
        float4 w = w4[idx], m = m4[idx], sv = s4[idx];
        xm += w.x * m.x + w.y * m.y + w.z * m.z + w.w * m.w;
        xs += w.x * sv.x + w.y * sv.y + w.z * sv.z + w.w * sv.w;
    }
#pragma unroll
    for (int o = 16; o > 0; o >>= 1) {
        xm += __shfl_xor_sync(0xffffffffu, xm, o);
        xs += __shfl_xor_sync(0xffffffffu, xs, o);
    }
    if (lane == 0) {
        const float inv_sqrt_d = 0.08838834764831843f;
        g_km[row] = xm * inv_sqrt_d;
        g_ks[row] = xs * inv_sqrt_d;
    }
}

// ----------------------------------------------------------------------------
// per (h,q): mu = sigmoid(q.km); sg = max(softplus(q.ks), 1e-4);
// hoisted per-parity Gaussian params amp_p, c_p.
// ----------------------------------------------------------------------------
__global__ __launch_bounds__(256) void musig_kernel(const float* __restrict__ q) {
    int warp = threadIdx.x >> 5, lane = threadIdx.x & 31;
    int row = blockIdx.x * 8 + warp;
    int h = row >> 11;
    float4 qv = reinterpret_cast<const float4*>(q + (size_t)row * D_)[lane];
    float4 km = reinterpret_cast<const float4*>(g_km + h * D_)[lane];
    float4 ks = reinterpret_cast<const float4*>(g_ks + h * D_)[lane];
    float xm = qv.x * km.x + qv.y * km.y + qv.z * km.z + qv.w * km.w;
    float xs = qv.x * ks.x + qv.y * ks.y + qv.z * ks.z + qv.w * ks.w;
#pragma unroll
    for (int o = 16; o > 0; o >>= 1) {
        xm += __shfl_xor_sync(0xffffffffu, xm, o);
        xs += __shfl_xor_sync(0xffffffffu, xs, o);
    }
    if (lane == 0) {
        const float INV_SQRT_2PI = 0.3989422804014327f;
        const float NHALF_LOG2E  = -0.7213475204444817f;
        float m_ = 1.f / (1.f + expf(-xm));
        float sp = fmaxf(xs, 0.f) + log1pf(expf(-fabsf(xs)));
        float sg = fmaxf(sp, 1e-4f);
        g_mu[row] = m_;
        float inv0 = rsqrtf(sg + 2.5e-5f);
        float inv1 = rsqrtf(sg + 1.0e-4f);
        g_amp[0][row] = inv0 * INV_SQRT_2PI;
        g_amp[1][row] = inv1 * INV_SQRT_2PI;
        g_c2[0][row]  = NHALF_LOG2E * inv0 * inv0;
        g_c2[1][row]  = NHALF_LOG2E * inv1 * inv1;
    }
}

// ----------------------------------------------------------------------------
// Fused r + context GEMM per head (fp32 FFMA, fast_exp2 on FMA pipe)
// ----------------------------------------------------------------------------
__global__ __launch_bounds__(256) void ctx_kernel() {
    __shared__ float Rs[BKK][BM + 4];
    __shared__ float Vs[BKK][BN + 4];
    __shared__ float mus[128], amps[2][128], c2s[2][128];

    int qt = blockIdx.x;
    int h  = blockIdx.y;
    int q0 = qt * 128;
    int t = threadIdx.x;
    int tx = t & 15, ty = t >> 4;

    if (t < 128) {
        int row = h * QL + q0 + t;
        mus[t]     = g_mu[row];
        amps[0][t] = g_amp[0][row];
        amps[1][t] = g_amp[1][row];
        c2s[0][t]  = g_c2[0][row];
        c2s[1][t]  = g_c2[1][row];
    }

    int vr = t >> 4;
    int vc = (t & 15) << 2;
    int q8 = (t & 15) << 3;
    const float* vbase = g_vals + h * D_;

    float acc[8][8] = {};
    __syncthreads();

    for (int n0 = 0; n0 < NB; n0 += BKK) {
        float4 v0 = *(const float4*)&vbase[(size_t)(n0 + vr) * DM + vc];
        float4 v1 = *(const float4*)&vbase[(size_t)(n0 + vr) * DM + vc + 64];
        int p = (n0 + vr) & 1;
        float bm = g_bmu[n0 + vr];
        float rloc[8];
#pragma unroll
        for (int j = 0; j < 8; j++) {
            float dx = bm - mus[q8 + j];
            float x = c2s[p][q8 + j] * dx * dx;
            rloc[j] = amps[p][q8 + j] * fast_exp2(x);
        }
        *(float4*)&Vs[vr][vc]      = v0;
        *(float4*)&Vs[vr][vc + 64] = v1;
#pragma unroll
        for (int j = 0; j < 8; j++) Rs[vr][q8 + j] = rloc[j];
        __syncthreads();
#pragma unroll
        for (int kk = 0; kk < BKK; kk++) {
            float4 a0 = *(float4*)&Rs[kk][ty << 3];
            float4 a1 = *(float4*)&Rs[kk][(ty << 3) + 4];
            float4 b0 = *(float4*)&Vs[kk][tx << 3];
            float4 b1 = *(float4*)&Vs[kk][(tx << 3) + 4];
            float av[8] = {a0.x, a0.y, a0.z, a0.w, a1.x, a1.y, a1.z, a1.w};
            float bv[8] = {b0.x, b0.y, b0.z, b0.w, b1.x, b1.y, b1.z, b1.w};
#pragma unroll
            for (int i = 0; i < 8; i++)
#pragma unroll
                for (int j = 0; j < 8; j++) acc[i][j] = fmaf(av[i], bv[j], acc[i][j]);
        }
        __syncthreads();
    }
    int qb = q0 + (ty << 3);
    int db = h * D_ + (tx << 3);
#pragma unroll
    for (int i = 0; i < 8; i++) {
        *(float4*)&g_ctx[(size_t)(qb + i) * DM + db]     = *(float4*)&acc[i][0];
        *(float4*)&g_ctx[(size_t)(qb + i) * DM + db + 4] = *(float4*)&acc[i][4];
    }
}

// ----------------------------------------------------------------------------
// launch
// ----------------------------------------------------------------------------
extern "C" void kernel_launch(void* const* d_in, const int* in_sizes, int n_in,
                              void* d_out, int out_size) {
    (void)in_sizes; (void)n_in; (void)out_size;
    const float* k_in = (const float*)d_in[0];
    const float* q_in = (const float*)d_in[1];
    const float* Wk   = (const float*)d_in[2];
    const float* Wv   = (const float*)d_in[3];
    const float* Wo   = (const float*)d_in[4];
    const float* wmu  = (const float*)d_in[5];
    const float* wsig = (const float*)d_in[6];

    compute_G_host();
    cudaMemcpyToSymbolAsync(g_G,   hostG,   sizeof(hostG),   0, cudaMemcpyHostToDevice, 0);
    cudaMemcpyToSymbolAsync(g_bmu, hostbmu, sizeof(hostbmu), 0, cudaMemcpyHostToDevice, 0);

    float *pB, *pVals, *pCtx, *pG;
    cudaGetSymbolAddress((void**)&pB,    g_B);
    cudaGetSymbolAddress((void**)&pVals, g_vals);
    cudaGetSymbolAddress((void**)&pCtx,  g_ctx);
    cudaGetSymbolAddress((void**)&pG,    g_G);
    __nv_bfloat16 *pBh, *pBl, *pWvh, *pWvl, *pWoh, *pWol, *pCh, *pCl;
    cudaGetSymbolAddress((void**)&pBh,  g_Bh);  cudaGetSymbolAddress((void**)&pBl,  g_Bl);
    cudaGetSymbolAddress((void**)&pWvh, g_Wvh); cudaGetSymbolAddress((void**)&pWvl, g_Wvl);
    cudaGetSymbolAddress((void**)&pWoh, g_Woh); cudaGetSymbolAddress((void**)&pWol, g_Wol);
    cudaGetSymbolAddress((void**)&pCh,  g_Ch);  cudaGetSymbolAddress((void**)&pCl,  g_Cl);

    cudaFuncSetAttribute(gemm_mma_nt,
                         cudaFuncAttributeMaxDynamicSharedMemorySize, GSMEM_B);

    const int n4B = NB * DM / 4, n4W = DM * DM / 4, n4C = QL * DM / 4;

    // B[n][e] = sum_l G[l][n] k[l][e]   (fp32)
    sgemm_tn_B<<<dim3(NB / BM, DM / BN), 256>>>(pG, k_in);

    // splits (Wk no longer needs splitting: keys GEMM is collapsed)
    split_kernel<<<(n4B + 255) / 256, 256>>>((const float4*)pB,
        (__nv_bfloat162*)pBh, (__nv_bfloat162*)pBl, n4B);
    split_kernel<<<(n4W + 255) / 256, 256>>>((const float4*)Wv,
        (__nv_bfloat162*)pWvh, (__nv_bfloat162*)pWvl, n4W);
    split_kernel<<<(n4W + 255) / 256, 256>>>((const float4*)Wo,
        (__nv_bfloat162*)pWoh, (__nv_bfloat162*)pWol, n4W);

    // vals = B Wv^T  -- tensor-core bf16-split
    gemm_mma_nt<<<dim3(NB / 128, DM / 128), 256, GSMEM_B>>>(
        pBh, pBl, pWvh, pWvl, pVals, DM, DM, 1.0f);

    // km/ks via collapsed keys GEMM: bv = B^T w, then Wk . bv
    bvec_part<<<dim3(DM / 128, 8), 128>>>(wmu, wsig);
    bvec_reduce<<<DM / 128, 128>>>();
    kmdot_kernel<<<DM / 8, 256>>>(Wk);
    musig_kernel<<<(H_ * QL) / 8, 256>>>(q_in);
    ctx_kernel<<<dim3(QL / BM, H_), 256>>>();

    // split ctx, then out = ctx Wo^T  -- tensor-core bf16-split
    split_kernel<<<(n4C + 255) / 256, 256>>>((const float4*)pCtx,
        (__nv_bfloat162*)pCh, (__nv_bfloat162*)pCl, n4C);
    gemm_mma_nt<<<dim3(QL / 128, DM / 128), 256, GSMEM_B>>>(
        pCh, pCl, pWoh, pWol, (float*)d_out, DM, DM, 1.0f);
}

// round 13
// speedup vs baseline: 2.9055x; 1.2850x over previous
#include <cuda_runtime.h>
#include <cuda_bf16.h>
#include <math.h>
#include <string.h>
#include <stdint.h>

// Problem constants
#define H_   16
#define D_   128
#define DM   2048   // H_*D_
#define NB   1024   // N_BASIS
#define MEM  512    // memory length (l)
#define QL   2048   // query length
#define NPOS 1024   // 2*l sample positions
#define BW   192    // half-bandwidth of F F^T + ridge

// mma GEMM tiling
#define GBK 16
#define GSTRIDE 24                       // smem row stride in bf16 (48B, conflict-free)
#define GTILE_B (128 * GSTRIDE * 2)      // bytes per tile (6144)
#define STAGE_B (4 * GTILE_B)            // 4 tiles per stage (24576)
#define GSMEM_B (3 * STAGE_B)            // 3 stages = 73728 B

// ctx kernel tiling: A(r) tiles use 40-elem (80B) row stride; V tiles use GSTRIDE
#define RT_STRIDE 40
#define RT_B (128 * RT_STRIDE * 2)       // 10240
#define CSTAGE_B (2 * RT_B + 2 * GTILE_B)// 32768
#define CSMEM_B (3 * CSTAGE_B)           // 98304

// ----------------------------------------------------------------------------
// Device scratch (static globals -- no allocation anywhere)
// ----------------------------------------------------------------------------
__device__ float g_B[NB * DM];       // fp32 B (needed for km/ks path)
__device__ float g_km[DM];
__device__ float g_ks[DM];
__device__ float g_pb[2][8][DM];
__device__ float g_bvmu[DM];
__device__ float g_bvsg[DM];
__device__ float g_mu[H_ * QL];
__device__ float g_amp[2][H_ * QL];
__device__ float g_c2[2][H_ * QL];
__device__ float g_bmu[NB];

// bf16 split operands
__device__ __nv_bfloat16 g_GTh[NB * MEM], g_GTl[NB * MEM];   // G^T (host-filled)
__device__ __nv_bfloat16 g_kTh[DM * MEM], g_kTl[DM * MEM];   // k^T
__device__ __nv_bfloat16 g_Bh[NB * DM],  g_Bl[NB * DM];
__device__ __nv_bfloat16 g_Wvh[DM * DM], g_Wvl[DM * DM];
__device__ __nv_bfloat16 g_Woh[DM * DM], g_Wol[DM * DM];
__device__ __nv_bfloat16 g_Vh[DM * NB],  g_Vl[DM * NB];      // V^T [hd][n]
__device__ __nv_bfloat16 g_Ch[QL * DM],  g_Cl[QL * DM];      // ctx [q][hd]

// ----------------------------------------------------------------------------
// Host-side constant: G = solve(F F^T + 0.5 I, F)^T [256:768], emitted as
// G^T bf16 hi/lo (pure function of compile-time constants).
// ----------------------------------------------------------------------------
static double hF[NB][NPOS];
static double hA[NB][NB];
static float    hostbmu[NB];
static uint16_t hostGTh[NB * MEM], hostGTl[NB * MEM];

static inline uint16_t f2bf(float x) {
    uint32_t u; memcpy(&u, &x, 4);
    uint32_t r = (u + 0x7FFFu + ((u >> 16) & 1u)) >> 16;
    return (uint16_t)r;
}
static inline float bf2f(uint16_t h) {
    uint32_t u = (uint32_t)h << 16; float f; memcpy(&f, &u, 4); return f;
}

static void compute_G_host() {
    static double mu[NB], sgv[NB], pos[NPOS];
    static int plo[NB], phi[NB];
    const double SQ2PI = 2.506628274631000502;

    for (int i = 0; i < NB; i++) {
        mu[i]  = (double)(i >> 1) / 511.0;
        sgv[i] = (i & 1) ? 0.01 : 0.005;
        hostbmu[i] = (float)mu[i];
    }
    double a = -0.5 + 1.0 / 1024.0;
    double b =  1.5 - 1.0 / 1024.0;
    double step = (b - a) / 1023.0;
    for (int p = 0; p < NPOS; p++) pos[p] = a + p * step;

    for (int i = 0; i < NB; i++) {
        int lo = NPOS, hi = -1;
        double inv = 1.0 / sgv[i];
        double amp = inv / SQ2PI;
        for (int p = 0; p < NPOS; p++) {
            double t = (pos[p] - mu[i]) * inv;
            if (t > -15.0 && t < 15.0) {
                hF[i][p] = exp(-0.5 * t * t) * amp;
                if (p < lo) lo = p;
                hi = p;
            } else hF[i][p] = 0.0;
        }
        plo[i] = lo; phi[i] = hi;
    }

    memset(hA, 0, sizeof(hA));
    for (int i = 0; i < NB; i++) {
        int jmax = (i + BW < NB) ? i + BW : NB - 1;
        for (int j = i; j <= jmax; j++) {
            int lo = plo[i] > plo[j] ? plo[i] : plo[j];
            int hi = phi[i] < phi[j] ? phi[i] : phi[j];
            double s = 0.0;
            for (int p = lo; p <= hi; p++) s += hF[i][p] * hF[j][p];
            hA[i][j] = s; hA[j][i] = s;
        }
        hA[i][i] += 0.5;
    }

    for (int j = 0; j < NB; j++) {
        int kmin = (j - BW > 0) ? j - BW : 0;
        double s = hA[j][j];
        for (int k = kmin; k < j; k++) s -= hA[j][k] * hA[j][k];
        double Ljj = sqrt(s);
        hA[j][j] = Ljj;
        double invL = 1.0 / Ljj;
        int imax = (j + BW < NB) ? j + BW : NB - 1;
        for (int i = j + 1; i <= imax; i++) {
            int k0 = (i - BW > kmin) ? i - BW : kmin;
            double t = hA[i][j];
            for (int k = k0; k < j; k++) t -= hA[i][k] * hA[j][k];
            hA[i][j] = t * invL;
        }
    }

    static double yv[NB], xv[NB];
    for (int p = 256; p < 768; p++) {
        for (int i = 0; i < NB; i++) {
            int k0 = (i - BW > 0) ? i - BW : 0;
            double s = hF[i][p];
            for (int k = k0; k < i; k++) s -= hA[i][k] * yv[k];
            yv[i] = s / hA[i][i];
        }
        for (int i = NB - 1; i >= 0; i--) {
            int k1 = (i + BW < NB) ? i + BW : NB - 1;
            double s = yv[i];
            for (int k = i + 1; k <= k1; k++) s -= hA[k][i] * xv[k];
            xv[i] = s / hA[i][i];
        }
        int l = p - 256;
        for (int n = 0; n < NB; n++) {
            float g = (float)xv[n];
            uint16_t h = f2bf(g);
            hostGTh[n * MEM + l] = h;
            hostGTl[n * MEM + l] = f2bf(g - bf2f(h));
        }
    }
}

// ----------------------------------------------------------------------------
// PTX helpers (sm_80-portable: ldmatrix / mma.sync / cp.async)
// ----------------------------------------------------------------------------
__device__ __forceinline__ uint32_t smem_u32(const void* p) {
    uint32_t a;
    asm("{ .reg .u64 t; cvta.to.shared.u64 t, %1; cvt.u32.u64 %0, t; }" : "=r"(a) : "l"(p));
    return a;
}
__device__ __forceinline__ void cpa16(uint32_t s, const void* g) {
    asm volatile("cp.async.cg.shared.global [%0], [%1], 16;" :: "r"(s), "l"(g));
}
#define CP_COMMIT() asm volatile("cp.async.commit_group;" ::: "memory")
#define CP_WAIT1()  asm volatile("cp.async.wait_group 1;" ::: "memory")
#define LDSM4(r0, r1, r2, r3, addr) \
    asm volatile("ldmatrix.sync.aligned.m8n8.x4.shared.b16 {%0,%1,%2,%3}, [%4];" \
                 : "=r"(r0), "=r"(r1), "=r"(r2), "=r"(r3) : "r"(addr))
#define MMA16816(c, a, b) \
    asm volatile("mma.sync.aligned.m16n8k16.row.col.f32.bf16.bf16.f32 " \
                 "{%0,%1,%2,%3}, {%4,%5,%6,%7}, {%8,%9}, {%0,%1,%2,%3};" \
                 : "+f"((c)[0]), "+f"((c)[1]), "+f"((c)[2]), "+f"((c)[3]) \
                 : "r"((a)[0]), "r"((a)[1]), "r"((a)[2]), "r"((a)[3]), \
                   "r"((b)[0]), "r"((b)[1]))

__device__ __forceinline__ uint32_t pack_bf2(float a, float b) {
    __nv_bfloat162 t = __halves2bfloat162(__float2bfloat16(a), __float2bfloat16(b));
    uint32_t u; memcpy(&u, &t, 4); return u;
}

// ----------------------------------------------------------------------------
// Tensor-core NT GEMM with bf16 split operands (3-stage cp.async pipeline):
// out[m][n] = scale * sum_k (Ahi+Alo)[m][k] * (Bhi+Blo)[n][k]  (lo*lo dropped)
// Epilogue writes optional fp32 C and/or bf16 hi/lo split C.
// ----------------------------------------------------------------------------
__global__ __launch_bounds__(256) void gemm_mma_nt(
    const __nv_bfloat16* __restrict__ Ahi, const __nv_bfloat16* __restrict__ Alo,
    const __nv_bfloat16* __restrict__ Bhi, const __nv_bfloat16* __restrict__ Blo,
    float* __restrict__ Cf, __nv_bfloat16* __restrict__ Ch,
    __nv_bfloat16* __restrict__ Cl, int ldc, int K, float scale)
{
    extern __shared__ char smraw[];
    uint32_t base = smem_u32(smraw);

    int tid = threadIdx.x, lane = tid & 31, wid = tid >> 5;
    int m0 = blockIdx.x * 128, n0 = blockIdx.y * 128;
    int wm = (wid & 3) << 5;
    int wn = (wid >> 2) << 6;

    float acc[2][8][4];
#pragma unroll
    for (int i = 0; i < 2; i++)
#pragma unroll
        for (int j = 0; j < 8; j++)
#pragma unroll
            for (int l = 0; l < 4; l++) acc[i][j][l] = 0.f;

    int r = tid >> 1, hf = tid & 1;
    const __nv_bfloat16* gA0 = Ahi + (size_t)(m0 + r) * K + hf * 8;
    const __nv_bfloat16* gA1 = Alo + (size_t)(m0 + r) * K + hf * 8;
    const __nv_bfloat16* gB0 = Bhi + (size_t)(n0 + r) * K + hf * 8;
    const __nv_bfloat16* gB1 = Blo + (size_t)(n0 + r) * K + hf * 8;
    uint32_t soff = (uint32_t)(r * GSTRIDE + hf * 8) * 2;

    const int NT = K / GBK;

#pragma unroll
    for (int p = 0; p < 2; p++) {
        uint32_t sb = base + p * STAGE_B + soff;
        int k0 = p * GBK;
        cpa16(sb,               gA0 + k0);
        cpa16(sb + GTILE_B,     gA1 + k0);
        cpa16(sb + 2 * GTILE_B, gB0 + k0);
        cpa16(sb + 3 * GTILE_B, gB1 + k0);
        CP_COMMIT();
    }

    uint32_t a_off = ((uint32_t)((lane & 15)) * GSTRIDE + ((lane >> 4) << 3)) * 2;
    uint32_t b_off = ((uint32_t)((lane & 7) + ((lane & 16) ? 8 : 0)) * GSTRIDE +
                     ((lane & 8) ? 8 : 0)) * 2;

    int s = 0;
    for (int it = 0; it < NT; it++) {
        CP_WAIT1();
        __syncthreads();

        if (it + 2 < NT) {
            int s2 = s + 2; if (s2 >= 3) s2 -= 3;
            uint32_t sb = base + s2 * STAGE_B + soff;
            int k0 = (it + 2) * GBK;
            cpa16(sb,               gA0 + k0);
            cpa16(sb + GTILE_B,     gA1 + k0);
            cpa16(sb + 2 * GTILE_B, gB0 + k0);
            cpa16(sb + 3 * GTILE_B, gB1 + k0);
        }
        CP_COMMIT();

        uint32_t tb = base + s * STAGE_B;

        uint32_t ah[2][4], al[2][4];
        {
            uint32_t ad = tb + (uint32_t)wm * GSTRIDE * 2 + a_off;
            LDSM4(ah[0][0], ah[0][1], ah[0][2], ah[0][3], ad);
            LDSM4(ah[1][0], ah[1][1], ah[1][2], ah[1][3], ad + 16 * GSTRIDE * 2);
            uint32_t adl = ad + GTILE_B;
            LDSM4(al[0][0], al[0][1], al[0][2], al[0][3], adl);
            LDSM4(al[1][0], al[1][1], al[1][2], al[1][3], adl + 16 * GSTRIDE * 2);
        }
        uint32_t bh[8][2], bl[8][2];
        {
            uint32_t bd = tb + 2 * GTILE_B + (uint32_t)wn * GSTRIDE * 2 + b_off;
#pragma unroll
            for (int j = 0; j < 4; j++) {
                uint32_t ad = bd + (uint32_t)j * 16 * GSTRIDE * 2;
                LDSM4(bh[2 * j][0], bh[2 * j][1], bh[2 * j + 1][0], bh[2 * j + 1][1], ad);
                LDSM4(bl[2 * j][0], bl[2 * j][1], bl[2 * j + 1][0], bl[2 * j + 1][1],
                      ad + GTILE_B);
            }
        }

#pragma unroll
        for (int mt = 0; mt < 2; mt++)
#pragma unroll
            for (int nt = 0; nt < 8; nt++) {
                MMA16816(acc[mt][nt], ah[mt], bh[nt]);
                MMA16816(acc[mt][nt], ah[mt], bl[nt]);
                MMA16816(acc[mt][nt], al[mt], bh[nt]);
            }
        s++; if (s >= 3) s -= 3;
    }

    // epilogue
    int erow = lane >> 2;
    int ecol = (lane & 3) << 1;
#pragma unroll
    for (int mt = 0; mt < 2; mt++)
#pragma unroll
        for (int nt = 0; nt < 8; nt++) {
            int row = m0 + wm + mt * 16 + erow;
            int col = n0 + wn + nt * 8 + ecol;
            float v00 = acc[mt][nt][0] * scale, v01 = acc[mt][nt][1] * scale;
            float v10 = acc[mt][nt][2] * scale, v11 = acc[mt][nt][3] * scale;
            size_t i0 = (size_t)row * ldc + col;
            size_t i1 = (size_t)(row + 8) * ldc + col;
            if (Cf) {
                *(float2*)&Cf[i0] = make_float2(v00, v01);
                *(float2*)&Cf[i1] = make_float2(v10, v11);
            }
            if (Ch) {
                __nv_bfloat16 h00 = __float2bfloat16(v00), h01 = __float2bfloat16(v01);
                __nv_bfloat16 h10 = __float2bfloat16(v10), h11 = __float2bfloat16(v11);
                *(__nv_bfloat162*)&Ch[i0] = __halves2bfloat162(h00, h01);
                *(__nv_bfloat162*)&Ch[i1] = __halves2bfloat162(h10, h11);
                *(__nv_bfloat162*)&Cl[i0] = __halves2bfloat162(
                    __float2bfloat16(v00 - __bfloat162float(h00)),
                    __float2bfloat16(v01 - __bfloat162float(h01)));
                *(__nv_bfloat162*)&Cl[i1] = __halves2bfloat162(
                    __float2bfloat16(v10 - __bfloat162float(h10)),
                    __float2bfloat16(v11 - __bfloat162float(h11)));
            }
        }
}

// ----------------------------------------------------------------------------
// fast exp2 on the FMA pipe (x <= 0), no MUFU.
// ----------------------------------------------------------------------------
__device__ __forceinline__ float fast_exp2(float x) {
    x = fmaxf(x, -126.0f);
    float fl = floorf(x);
    float f = x - fl;
    float p =        1.8775767e-3f;
    p = fmaf(p, f,   8.9893397e-3f);
    p = fmaf(p, f,   5.5826318e-2f);
    p = fmaf(p, f,   2.4015361e-1f);
    p = fmaf(p, f,   6.9315308e-1f);
    p = fmaf(p, f,   9.9999994e-1f);
    int e = __float2int_rn(fl);
    float s = __int_as_float((e + 127) << 23);
    return p * s;
}

// ----------------------------------------------------------------------------
// Fused ctx kernel on tensor cores. Grid (q tiles = 16, heads = 16).
// ctx[q][h*128+d] = sum_n r(h,q,n) * V^T[h*128+d][n]
// r computed on FMA pipe each n-chunk, split to bf16 hi/lo in smem (A tile);
// V^T hi/lo streamed via 3-stage cp.async. Epilogue writes Ch/Cl bf16 split.
// Stage layout: [Rh(10240) | Rl(10240) | Vh(6144) | Vl(6144)]
// ----------------------------------------------------------------------------
__global__ __launch_bounds__(256) void ctx_mma() {
    extern __shared__ char smraw[];
    uint32_t base = smem_u32(smraw);
    char* smp = smraw;

    int tid = threadIdx.x, lane = tid & 31, wid = tid >> 5;
    int q0 = blockIdx.x * 128;
    int h  = blockIdx.y;
    int wm = (wid & 3) << 5;
    int wn = (wid >> 2) << 6;

    float acc[2][8][4];
#pragma unroll
    for (int i = 0; i < 2; i++)
#pragma unroll
        for (int j = 0; j < 8; j++)
#pragma unroll
            for (int l = 0; l < 4; l++) acc[i][j][l] = 0.f;

    // V cp.async mapping
    int vrow = tid >> 1, hf = tid & 1;
    const __nv_bfloat16* gV0 = g_Vh + (size_t)(h * 128 + vrow) * NB + hf * 8;
    const __nv_bfloat16* gV1 = g_Vl + (size_t)(h * 128 + vrow) * NB + hf * 8;
    uint32_t vsoff = (uint32_t)(vrow * GSTRIDE + hf * 8) * 2;

    // r mapping: thread -> (q row, n-group of 8)
    int rq = tid & 127;
    int ng = tid >> 7;           // 0 or 1
    float mu_q, a0_q, a1_q, c0_q, c1_q;
    {
        int row = h * QL + q0 + rq;
        mu_q = g_mu[row];
        a0_q = g_amp[0][row]; a1_q = g_amp[1][row];
        c0_q = g_c2[0][row];  c1_q = g_c2[1][row];
    }
    uint32_t rsoff = (uint32_t)(rq * RT_STRIDE + ng * 8) * 2;

    // prologue: V stages 0,1
#pragma unroll
    for (int p = 0; p < 2; p++) {
        uint32_t sb = base + p * CSTAGE_B + 2 * RT_B + vsoff;
        cpa16(sb,           gV0 + p * GBK);
        cpa16(sb + GTILE_B, gV1 + p * GBK);
        CP_COMMIT();
    }

    uint32_t a_off = ((uint32_t)((lane & 15)) * RT_STRIDE + ((lane >> 4) << 3)) * 2;
    uint32_t b_off = ((uint32_t)((lane & 7) + ((lane & 16) ? 8 : 0)) * GSTRIDE +
                     ((lane & 8) ? 8 : 0)) * 2;

    const int NT = NB / GBK;   // 64
    int s = 0;
    for (int it = 0; it < NT; it++) {
        CP_WAIT1();
        __syncthreads();

        if (it + 2 < NT) {
            int s2 = s + 2; if (s2 >= 3) s2 -= 3;
            uint32_t sb = base + s2 * CSTAGE_B + 2 * RT_B + vsoff;
            cpa16(sb,           gV0 + (it + 2) * GBK);
            cpa16(sb + GTILE_B, gV1 + (it + 2) * GBK);
        }
        CP_COMMIT();

        // compute r for 8 consecutive n (parity alternates with j), pack bf16
        {
            int nb8 = it * 16 + ng * 8;
            uint32_t ph[4], pl[4];
#pragma unroll
            for (int jj = 0; jj < 4; jj++) {
                float bm0 = g_bmu[nb8 + 2 * jj];
                float bm1 = g_bmu[nb8 + 2 * jj + 1];
                float dx0 = bm0 - mu_q, dx1 = bm1 - mu_q;
                float r0 = a0_q * fast_exp2(c0_q * dx0 * dx0);
                float r1 = a1_q * fast_exp2(c1_q * dx1 * dx1);
                __nv_bfloat16 h0 = __float2bfloat16(r0);
                __nv_bfloat16 h1 = __float2bfloat16(r1);
                ph[jj] = pack_bf2(r0, r1);   // hi pair (recomputes rn internally)
                // lo pair
                pl[jj] = pack_bf2(r0 - __bfloat162float(h0),
                                  r1 - __bfloat162float(h1));
            }
            char* dst = smp + s * CSTAGE_B + rsoff;
            *(uint4*)dst          = make_uint4(ph[0], ph[1], ph[2], ph[3]);
            *(uint4*)(dst + RT_B) = make_uint4(pl[0], pl[1], pl[2], pl[3]);
        }
        __syncthreads();

        uint32_t tb = base + s * CSTAGE_B;

        uint32_t ah[2][4], al[2][4];
        {
            uint32_t ad = tb + (uint32_t)wm * RT_STRIDE * 2 + a_off;
            LDSM4(ah[0][0], ah[0][1], ah[0][2], ah[0][3], ad);
            LDSM4(ah[1][0], ah[1][1], ah[1][2], ah[1][3], ad + 16 * RT_STRIDE * 2);
            uint32_t adl = ad + RT_B;
            LDSM4(al[0][0], al[0][1], al[0][2], al[0][3], adl);
            LDSM4(al[1][0], al[1][1], al[1][2], al[1][3], adl + 16 * RT_STRIDE * 2);
        }
        uint32_t bh[8][2], bl[8][2];
        {
            uint32_t bd = tb + 2 * RT_B + (uint32_t)wn * GSTRIDE * 2 + b_off;
#pragma unroll
            for (int j = 0; j < 4; j++) {
                uint32_t ad = bd + (uint32_t)j * 16 * GSTRIDE * 2;
                LDSM4(bh[2 * j][0], bh[2 * j][1], bh[2 * j + 1][0], bh[2 * j + 1][1], ad);
                LDSM4(bl[2 * j][0], bl[2 * j][1], bl[2 * j + 1][0], bl[2 * j + 1][1],
                      ad + GTILE_B);
            }
        }

#pragma unroll
        for (int mt = 0; mt < 2; mt++)
#pragma unroll
            for (int nt = 0; nt < 8; nt++) {
                MMA16816(acc[mt][nt], ah[mt], bh[nt]);
                MMA16816(acc[mt][nt], ah[mt], bl[nt]);
                MMA16816(acc[mt][nt], al[mt], bh[nt]);
            }
        s++; if (s >= 3) s -= 3;
    }

    // epilogue: write ctx bf16 hi/lo
    int erow = lane >> 2;
    int ecol = (lane & 3) << 1;
#pragma unroll
    for (int mt = 0; mt < 2; mt++)
#pragma unroll
        for (int nt = 0; nt < 8; nt++) {
            int row = q0 + wm + mt * 16 + erow;
            int col = h * 128 + wn + nt * 8 + ecol;
            float v00 = acc[mt][nt][0], v01 = acc[mt][nt][1];
            float v10 = acc[mt][nt][2], v11 = acc[mt][nt][3];
            size_t i0 = (size_t)row * DM + col;
            size_t i1 = (size_t)(row + 8) * DM + col;
            __nv_bfloat16 h00 = __float2bfloat16(v00), h01 = __float2bfloat16(v01);
            __nv_bfloat16 h10 = __float2bfloat16(v10), h11 = __float2bfloat16(v11);
            *(__nv_bfloat162*)&g_Ch[i0] = __halves2bfloat162(h00, h01);
            *(__nv_bfloat162*)&g_Ch[i1] = __halves2bfloat162(h10, h11);
            *(__nv_bfloat162*)&g_Cl[i0] = __halves2bfloat162(
                __float2bfloat16(v00 - __bfloat162float(h00)),
                __float2bfloat16(v01 - __bfloat162float(h01)));
            *(__nv_bfloat162*)&g_Cl[i1] = __halves2bfloat162(
                __float2bfloat16(v10 - __bfloat162float(h10)),
                __float2bfloat16(v11 - __bfloat162float(h11)));
        }
}

// ----------------------------------------------------------------------------
// split fp32 -> bf16 hi/lo (weights)
// ----------------------------------------------------------------------------
__global__ __launch_bounds__(256) void split_kernel(
    const float4* __restrict__ src, __nv_bfloat162* __restrict__ hi,
    __nv_bfloat162* __restrict__ lo, int n4)
{
    int i = blockIdx.x * 256 + threadIdx.x;
    if (i >= n4) return;
    float4 v = src[i];
    __nv_bfloat16 h0 = __float2bfloat16(v.x);
    __nv_bfloat16 h1 = __float2bfloat16(v.y);
    __nv_bfloat16 h2 = __float2bfloat16(v.z);
    __nv_bfloat16 h3 = __float2bfloat16(v.w);
    hi[2 * i]     = __halves2bfloat162(h0, h1);
    hi[2 * i + 1] = __halves2bfloat162(h2, h3);
    lo[2 * i]     = __halves2bfloat162(
        __float2bfloat16(v.x - __bfloat162float(h0)),
        __float2bfloat16(v.y - __bfloat162float(h1)));
    lo[2 * i + 1] = __halves2bfloat162(
        __float2bfloat16(v.z - __bfloat162float(h2)),
        __float2bfloat16(v.w - __bfloat162float(h3)));
}

// ----------------------------------------------------------------------------
// transpose+split k: [512][2048] fp32 -> kTh/kTl [2048][512] bf16
// ----------------------------------------------------------------------------
__global__ __launch_bounds__(256) void transpose_split_k(const float* __restrict__ kin) {
    __shared__ float t[32][33];
    int e0 = blockIdx.x * 32, l0 = blockIdx.y * 32;
    int tx = threadIdx.x & 31, ty = threadIdx.x >> 5;   // ty 0..7
#pragma unroll
    for (int i = 0; i < 4; i++) {
        int l = ty + i * 8;
        t[l][tx] = kin[(size_t)(l0 + l) * DM + e0 + tx];
    }
    __syncthreads();
#pragma unroll
    for (int i = 0; i < 4; i++) {
        int er = ty + i * 8;
        float v = t[tx][er];
        __nv_bfloat16 hb = __float2bfloat16(v);
        size_t idx = (size_t)(e0 + er) * MEM + l0 + tx;
        g_kTh[idx] = hb;
        g_kTl[idx] = __float2bfloat16(v - __bfloat162float(hb));
    }
}

// ----------------------------------------------------------------------------
// bvec: bv_mu[e] = sum_n B[n][e]*wmu[n]; two-stage partials
// ----------------------------------------------------------------------------
__global__ __launch_bounds__(128) void bvec_part(
    const float* __restrict__ wmu, const float* __restrict__ wsig)
{
    int e = blockIdx.x * 128 + threadIdx.x;
    int c = blockIdx.y;
    float sm = 0.f, ss = 0.f;
    int nbeg = c * 128;
    for (int n = nbeg; n < nbeg + 128; n++) {
        float b = g_B[(size_t)n * DM + e];
        sm += b * wmu[n];
        ss += b * wsig[n];
    }
    g_pb[0][c][e] = sm;
    g_pb[1][c][e] = ss;
}

__global__ __launch_bounds__(128) void bvec_reduce() {
    int e = blockIdx.x * 128 + threadIdx.x;
    float a = 0.f, b = 0.f;
#pragma unroll
    for (int c = 0; c < 8; c++) { a += g_pb[0][c][e]; b += g_pb[1][c][e]; }
    g_bvmu[e] = a;
    g_bvsg[e] = b;
}

// ----------------------------------------------------------------------------
// km[i] = (Wk[i,:].bv_mu)/sqrt(D), ks likewise
// ----------------------------------------------------------------------------
__global__ __launch_bounds__(256) void kmdot_kernel(const float* __restrict__ Wk) {
    int warp = threadIdx.x >> 5, lane = threadIdx.x & 31;
    int row = blockIdx.x * 8 + warp;
    const float4* w4 = (const float4*)(Wk + (size_t)row * DM);
    const float4* m4 = (const float4*)g_bvmu;
    const float4* s4 = (const float4*)g_bvsg;
    float xm = 0.f, xs = 0.f;
#pragma unroll
    for (int it = 0; it < 16; it++) {
        int idx = it * 32 + lane;
        float4 w = w4[idx], m = m4[idx], sv = s4[idx];
        xm += w.x * m.x + w.y * m.y + w.z * m.z + w.w * m.w;
        xs += w.x * sv.x + w.y * sv.y + w.z * sv.z + w.w * sv.w;
    }
#pragma unroll
    for (int o = 16; o > 0; o >>= 1) {
        xm += __shfl_xor_sync(0xffffffffu, xm, o);
        xs += __shfl_xor_sync(0xffffffffu, xs, o);
    }
    if (lane == 0) {
        const float inv_sqrt_d = 0.08838834764831843f;
        g_km[row] = xm * inv_sqrt_d;
        g_ks[row] = xs * inv_sqrt_d;
    }
}

// ----------------------------------------------------------------------------
// per (h,q): mu = sigmoid(q.km); sg = max(softplus(q.ks), 1e-4);
// hoisted per-parity Gaussian params amp_p, c_p.
// ----------------------------------------------------------------------------
__global__ __launch_bounds__(256) void musig_kernel(const float* __restrict__ q) {
    int warp = threadIdx.x >> 5, lane = threadIdx.x & 31;
    int row = blockIdx.x * 8 + warp;
    int h = row >> 11;
    float4 qv = reinterpret_cast<const float4*>(q + (size_t)row * D_)[lane];
    float4 km = reinterpret_cast<const float4*>(g_km + h * D_)[lane];
    float4 ks = reinterpret_cast<const float4*>(g_ks + h * D_)[lane];
    float xm = qv.x * km.x + qv.y * km.y + qv.z * km.z + qv.w * km.w;
    float xs = qv.x * ks.x + qv.y * ks.y + qv.z * ks.z + qv.w * ks.w;
#pragma unroll
    for (int o = 16; o > 0; o >>= 1) {
        xm += __shfl_xor_sync(0xffffffffu, xm, o);
        xs += __shfl_xor_sync(0xffffffffu, xs, o);
    }
    if (lane == 0) {
        const float INV_SQRT_2PI = 0.3989422804014327f;
        const float NHALF_LOG2E  = -0.7213475204444817f;
        float m_ = 1.f / (1.f + expf(-xm));
        float sp = fmaxf(xs, 0.f) + log1pf(expf(-fabsf(xs)));
        float sg = fmaxf(sp, 1e-4f);
        g_mu[row] = m_;
        float inv0 = rsqrtf(sg + 2.5e-5f);
        float inv1 = rsqrtf(sg + 1.0e-4f);
        g_amp[0][row] = inv0 * INV_SQRT_2PI;
        g_amp[1][row] = inv1 * INV_SQRT_2PI;
        g_c2[0][row]  = NHALF_LOG2E * inv0 * inv0;
        g_c2[1][row]  = NHALF_LOG2E * inv1 * inv1;
    }
}

// ----------------------------------------------------------------------------
// launch
// ----------------------------------------------------------------------------
extern "C" void kernel_launch(void* const* d_in, const int* in_sizes, int n_in,
                              void* d_out, int out_size) {
    (void)in_sizes; (void)n_in; (void)out_size;
    const float* k_in = (const float*)d_in[0];
    const float* q_in = (const float*)d_in[1];
    const float* Wk   = (const float*)d_in[2];
    const float* Wv   = (const float*)d_in[3];
    const float* Wo   = (const float*)d_in[4];
    const float* wmu  = (const float*)d_in[5];
    const float* wsig = (const float*)d_in[6];

    compute_G_host();
    cudaMemcpyToSymbolAsync(g_GTh, hostGTh, sizeof(hostGTh), 0, cudaMemcpyHostToDevice, 0);
    cudaMemcpyToSymbolAsync(g_GTl, hostGTl, sizeof(hostGTl), 0, cudaMemcpyHostToDevice, 0);
    cudaMemcpyToSymbolAsync(g_bmu, hostbmu, sizeof(hostbmu), 0, cudaMemcpyHostToDevice, 0);

    float* pB;
    cudaGetSymbolAddress((void**)&pB, g_B);
    __nv_bfloat16 *pGTh, *pGTl, *pkTh, *pkTl, *pBh, *pBl;
    __nv_bfloat16 *pWvh, *pWvl, *pWoh, *pWol, *pVh, *pVl, *pCh, *pCl;
    cudaGetSymbolAddress((void**)&pGTh, g_GTh); cudaGetSymbolAddress((void**)&pGTl, g_GTl);
    cudaGetSymbolAddress((void**)&pkTh, g_kTh); cudaGetSymbolAddress((void**)&pkTl, g_kTl);
    cudaGetSymbolAddress((void**)&pBh,  g_Bh);  cudaGetSymbolAddress((void**)&pBl,  g_Bl);
    cudaGetSymbolAddress((void**)&pWvh, g_Wvh); cudaGetSymbolAddress((void**)&pWvl, g_Wvl);
    cudaGetSymbolAddress((void**)&pWoh, g_Woh); cudaGetSymbolAddress((void**)&pWol, g_Wol);
    cudaGetSymbolAddress((void**)&pVh,  g_Vh);  cudaGetSymbolAddress((void**)&pVl,  g_Vl);
    cudaGetSymbolAddress((void**)&pCh,  g_Ch);  cudaGetSymbolAddress((void**)&pCl,  g_Cl);

    cudaFuncSetAttribute(gemm_mma_nt,
                         cudaFuncAttributeMaxDynamicSharedMemorySize, GSMEM_B);
    cudaFuncSetAttribute(ctx_mma,
                         cudaFuncAttributeMaxDynamicSharedMemorySize, CSMEM_B);

    const int n4W = DM * DM / 4;

    // k^T split, then B = G^T k^T  (mma; epilogue writes fp32 B + Bh/Bl)
    transpose_split_k<<<dim3(DM / 32, MEM / 32), 256>>>(k_in);
    gemm_mma_nt<<<dim3(NB / 128, DM / 128), 256, GSMEM_B>>>(
        pGTh, pGTl, pkTh, pkTl, pB, pBh, pBl, DM, MEM, 1.0f);

    // weight splits
    split_kernel<<<(n4W + 255) / 256, 256>>>((const float4*)Wv,
        (__nv_bfloat162*)pWvh, (__nv_bfloat162*)pWvl, n4W);
    split_kernel<<<(n4W + 255) / 256, 256>>>((const float4*)Wo,
        (__nv_bfloat162*)pWoh, (__nv_bfloat162*)pWol, n4W);

    // V^T = Wv B^T  (mma; epilogue writes Vh/Vl bf16 only), [hd][n]
    gemm_mma_nt<<<dim3(DM / 128, NB / 128), 256, GSMEM_B>>>(
        pWvh, pWvl, pBh, pBl, nullptr, pVh, pVl, NB, DM, 1.0f);

    // km/ks collapsed keys path
    bvec_part<<<dim3(DM / 128, 8), 128>>>(wmu, wsig);
    bvec_reduce<<<DM / 128, 128>>>();
    kmdot_kernel<<<DM / 8, 256>>>(Wk);
    musig_kernel<<<(H_ * QL) / 8, 256>>>(q_in);

    // ctx on tensor cores (writes Ch/Cl directly)
    ctx_mma<<<dim3(QL / 128, H_), 256, CSMEM_B>>>();

    // out = ctx Wo^T  (mma; fp32 output)
    gemm_mma_nt<<<dim3(QL / 128, DM / 128), 256, GSMEM_B>>>(
        pCh, pCl, pWoh, pWol, (float*)d_out, nullptr, nullptr, DM, DM, 1.0f);
}